// round 15
// baseline (speedup 1.0000x reference)
#include <cuda_runtime.h>
#include <cuda_bf16.h>
#include <cstdint>

typedef unsigned long long ull;

#define NMAX 100032
#define EMAX 1664000
#define HID 64

// ---------------- packed fp32x2 helpers ----------------
__device__ __forceinline__ ull fma2(ull a, ull b, ull c) {
    ull d;
    asm("fma.rn.f32x2 %0, %1, %2, %3;" : "=l"(d) : "l"(a), "l"(b), "l"(c));
    return d;
}
__device__ __forceinline__ ull pack2(float x, float y) {
    ull r; asm("mov.b64 %0, {%1, %2};" : "=l"(r) : "f"(x), "f"(y)); return r;
}
__device__ __forceinline__ float2 unpack2(ull v) {
    float2 r; asm("mov.b64 {%0, %1}, %2;" : "=f"(r.x), "=f"(r.y) : "l"(v)); return r;
}
// bf16x2 word -> packed f32x2 (both halves masked; R7 lesson)
__device__ __forceinline__ ull bf2_to_f2x2(uint32_t u) {
    return ((ull)(u & 0xFFFF0000u) << 32) | ((ull)(u & 0x0000FFFFu) << 16);
}

__device__ __forceinline__ void cp16(void* smem, const void* gmem) {
    unsigned saddr = (unsigned)__cvta_generic_to_shared(smem);
    asm volatile("cp.async.cg.shared.global [%0], [%1], 16;" :: "r"(saddr), "l"(gmem));
}
__device__ __forceinline__ void cp_commit() { asm volatile("cp.async.commit_group;"); }
template <int N>
__device__ __forceinline__ void cp_wait() { asm volatile("cp.async.wait_group %0;" :: "n"(N)); }

__device__ __forceinline__ float gelu_tanh(float x) {
    float x3 = x * x * x;
    return 0.5f * x * (1.0f + tanhf(0.79788456080286535588f * (x + 0.044715f * x3)));
}

// bf16 mma (sm_80+)
#define MMA_BF16(d, a0, a1, a2, a3, b0, b1) \
    asm volatile( \
        "mma.sync.aligned.m16n8k16.row.col.f32.bf16.bf16.f32 " \
        "{%0,%1,%2,%3},{%4,%5,%6,%7},{%8,%9},{%0,%1,%2,%3};" \
        : "+f"((d)[0]), "+f"((d)[1]), "+f"((d)[2]), "+f"((d)[3]) \
        : "r"(a0), "r"(a1), "r"(a2), "r"(a3), "r"(b0), "r"(b1))

__device__ __forceinline__ uint32_t f2_to_bf2(float2 v) {
    __nv_bfloat162 b = __float22bfloat162_rn(v);
    return *(uint32_t*)&b;
}
__device__ __forceinline__ float2 bf2_to_f2(uint32_t u) {
    return __bfloat1622float2(*(__nv_bfloat162*)&u);
}

// ---------------- scratch ----------------
__device__ float g_h0 [NMAX * HID];
__device__ float g_h1 [NMAX * HID];
__device__ __nv_bfloat16 g_qb[NMAX * 64];
__device__ __nv_bfloat16 g_km[NMAX * 128];   // [kT'(64) | mT(64)] per node
__device__ uint2 g_Bhi[48 * 8 * 32];
__device__ uint2 g_Blo[48 * 8 * 32];
__device__ uint2 g_Chi[2 * 4 * 24 * 32];
__device__ uint2 g_Clo[2 * 4 * 24 * 32];
__device__ uint2 g_WoFhi[2 * 4 * 8 * 32];
__device__ uint2 g_WoFlo[2 * 4 * 8 * 32];
__device__ float g_bc [2 * 192];
__device__ int   g_cnt [NMAX];
__device__ int   g_off [NMAX];
__device__ int   g_offmut[NMAX];
__device__ int   g_part[128];
__device__ int   g_csr [EMAX];

// =====================================================================
// W prep for proj
// =====================================================================
__global__ void wprep_kernel(const float* __restrict__ Wp,
                             uint2* __restrict__ bhi, uint2* __restrict__ blo)
{
    int e = blockIdx.x * 256 + threadIdx.x;
    if (e >= 48 * 8 * 32) return;
    int lane = e & 31;
    int nt   = (e >> 5) & 7;
    int t    = e >> 8;
    int g = lane >> 2, tig = lane & 3;
    int nn = nt * 8 + g;
    int kb = t * 16 + tig * 2;

    float v00 = Wp[(kb    ) * 64 + nn];
    float v01 = Wp[(kb + 1) * 64 + nn];
    float v10 = Wp[(kb + 8) * 64 + nn];
    float v11 = Wp[(kb + 9) * 64 + nn];

    uint32_t h0 = f2_to_bf2(make_float2(v00, v01));
    uint32_t h1 = f2_to_bf2(make_float2(v10, v11));
    float2 hf0 = bf2_to_f2(h0), hf1 = bf2_to_f2(h1);
    uint32_t l0 = f2_to_bf2(make_float2(v00 - hf0.x, v01 - hf0.y));
    uint32_t l1 = f2_to_bf2(make_float2(v10 - hf1.x, v11 - hf1.y));

    bhi[e] = make_uint2(h0, h1);
    blo[e] = make_uint2(l0, l1);
}

// =====================================================================
// Wo prep
// =====================================================================
__global__ void woprep_kernel(const float* __restrict__ Wo,
                              uint2* __restrict__ whi, uint2* __restrict__ wlo)
{
    int e = blockIdx.x * 256 + threadIdx.x;
    if (e >= 2048) return;
    int lane = e & 31;
    int nt   = (e >> 5) & 7;
    int ch   = (e >> 8) & 3;
    int l    = e >> 10;
    int g = lane >> 2, tig = lane & 3;
    int nn = nt * 8 + g;
    int kb = ch * 16 + tig * 2;
    const float* W = Wo + l * 4096;

    float v00 = W[(kb    ) * 64 + nn];
    float v01 = W[(kb + 1) * 64 + nn];
    float v10 = W[(kb + 8) * 64 + nn];
    float v11 = W[(kb + 9) * 64 + nn];

    uint32_t h0 = f2_to_bf2(make_float2(v00, v01));
    uint32_t h1 = f2_to_bf2(make_float2(v10, v11));
    float2 hf0 = bf2_to_f2(h0), hf1 = bf2_to_f2(h1);
    uint32_t l0 = f2_to_bf2(make_float2(v00 - hf0.x, v01 - hf0.y));
    uint32_t l1 = f2_to_bf2(make_float2(v10 - hf1.x, v11 - hf1.y));

    whi[e] = make_uint2(h0, h1);
    wlo[e] = make_uint2(l0, l1);
}

// =====================================================================
// Combined qkv weights (q | kT'*prel | mT), bias included
// =====================================================================
__device__ float wc_val(int l, int j, int c,
                        const float* Wk, const float* Wq, const float* Wv,
                        const float* Ar, const float* Mr, const float* prel)
{
    if (c < 64) return Wq[l * 4096 + j * 64 + c];
    if (c < 128) {
        int f = c - 64, hh = f >> 4, fi = f & 15;
        float s = 0.f;
#pragma unroll
        for (int d = 0; d < 16; d++)
            s += Wk[l * 4096 + j * 64 + hh * 16 + d] * Ar[l * 1024 + hh * 256 + d * 16 + fi];
        return s * (prel[l * 4 + hh] * 0.25f);
    }
    int f = c - 128, hh = f >> 4, fi = f & 15;
    float s = 0.f;
#pragma unroll
    for (int d = 0; d < 16; d++)
        s += Wv[l * 4096 + j * 64 + hh * 16 + d] * Mr[l * 1024 + hh * 256 + d * 16 + fi];
    return s;
}

__global__ void wcombpack_kernel(
    const float* __restrict__ Wk, const float* __restrict__ bk,
    const float* __restrict__ Wq, const float* __restrict__ bq,
    const float* __restrict__ Wv, const float* __restrict__ bv,
    const float* __restrict__ Ar, const float* __restrict__ Mr,
    const float* __restrict__ prel,
    uint2* __restrict__ chi, uint2* __restrict__ clo, float* __restrict__ bc)
{
    int e = blockIdx.x * 256 + threadIdx.x;
    if (e < 6144) {
        int lane = e & 31;
        int r    = e >> 5;
        int nt   = r % 24;
        int r2   = r / 24;
        int ch   = r2 & 3;
        int l    = r2 >> 2;
        int g = lane >> 2, tig = lane & 3;
        int nn = nt * 8 + g;
        int kb = ch * 16 + tig * 2;

        float v00 = wc_val(l, kb,     nn, Wk, Wq, Wv, Ar, Mr, prel);
        float v01 = wc_val(l, kb + 1, nn, Wk, Wq, Wv, Ar, Mr, prel);
        float v10 = wc_val(l, kb + 8, nn, Wk, Wq, Wv, Ar, Mr, prel);
        float v11 = wc_val(l, kb + 9, nn, Wk, Wq, Wv, Ar, Mr, prel);

        uint32_t h0 = f2_to_bf2(make_float2(v00, v01));
        uint32_t h1 = f2_to_bf2(make_float2(v10, v11));
        float2 hf0 = bf2_to_f2(h0), hf1 = bf2_to_f2(h1);
        uint32_t l0 = f2_to_bf2(make_float2(v00 - hf0.x, v01 - hf0.y));
        uint32_t l1 = f2_to_bf2(make_float2(v10 - hf1.x, v11 - hf1.y));
        chi[e] = make_uint2(h0, h1);
        clo[e] = make_uint2(l0, l1);
    } else if (e < 6144 + 384) {
        int e2 = e - 6144;
        int l = e2 / 192, c = e2 % 192;
        float v;
        if (c < 64) {
            v = bq[l * 64 + c];
        } else if (c < 128) {
            int f = c - 64, hh = f >> 4, fi = f & 15;
            float s = 0.f;
#pragma unroll
            for (int d = 0; d < 16; d++)
                s += bk[l * 64 + hh * 16 + d] * Ar[l * 1024 + hh * 256 + d * 16 + fi];
            v = s * (prel[l * 4 + hh] * 0.25f);
        } else {
            int f = c - 128, hh = f >> 4, fi = f & 15;
            float s = 0.f;
#pragma unroll
            for (int d = 0; d < 16; d++)
                s += bv[l * 64 + hh * 16 + d] * Mr[l * 1024 + hh * 256 + d * 16 + fi];
            v = s;
        }
        bc[e2] = v;
    }
}

// =====================================================================
// proj: h = x @ Wp + bp via bf16 3-term split HMMA (R11 version)
// =====================================================================
__device__ __forceinline__ int aswz(int row, int kp) {
    return row * 8 + (kp ^ ((row & 3) << 1));
}

__global__ __launch_bounds__(256) void proj_mma_kernel(
    const float* __restrict__ x, const float* __restrict__ bp,
    const uint2* __restrict__ gBhi, const uint2* __restrict__ gBlo,
    float* __restrict__ h, int n)
{
    __shared__ ull  sA[4][128 * 8];
    __shared__ uint2 sB[4][2][8][32];

    const int tid  = threadIdx.x;
    const int gm   = blockIdx.x * 128;
    const int warp = tid >> 5, lane = tid & 31;
    const int g    = lane >> 2, tig = lane & 3;
    const int rA0  = warp * 16 + g;
    const int rA1  = rA0 + 8;

    auto prefetch = [&](int t) {
        int buf = t & 3;
#pragma unroll
        for (int i = 0; i < 2; i++) {
            int c = tid + i * 256;
            int row = c >> 2;
            int kp2 = (c & 3) * 2;
            int slot = aswz(row, kp2);
            int grow = gm + row; if (grow >= n) grow = n - 1;
            cp16((char*)sA[buf] + slot * 8,
                 x + (size_t)grow * 768 + t * 16 + kp2 * 2);
        }
        {
            int hl = tid >> 7;
            int c  = tid & 127;
            const uint2* src = hl ? gBlo : gBhi;
            cp16((char*)&sB[buf][hl][0][0] + c * 16,
                 (const char*)(src + t * 256) + c * 16);
        }
    };

    float acc[8][4];
#pragma unroll
    for (int i = 0; i < 8; i++)
#pragma unroll
        for (int j = 0; j < 4; j++) acc[i][j] = 0.f;

    prefetch(0); cp_commit();
    prefetch(1); cp_commit();
    prefetch(2); cp_commit();

    for (int t = 0; t < 48; t++) {
        if (t + 2 < 48)      cp_wait<2>();
        else if (t + 1 < 48) cp_wait<1>();
        else                 cp_wait<0>();
        __syncthreads();
        if (t + 3 < 48) { prefetch(t + 3); cp_commit(); }

        const int buf = t & 3;
        float2 v0 = unpack2(sA[buf][aswz(rA0, tig    )]);
        float2 v1 = unpack2(sA[buf][aswz(rA1, tig    )]);
        float2 v2 = unpack2(sA[buf][aswz(rA0, tig + 4)]);
        float2 v3 = unpack2(sA[buf][aswz(rA1, tig + 4)]);

        uint32_t ah0 = f2_to_bf2(v0), ah1 = f2_to_bf2(v1);
        uint32_t ah2 = f2_to_bf2(v2), ah3 = f2_to_bf2(v3);
        float2 h0 = bf2_to_f2(ah0), h1 = bf2_to_f2(ah1);
        float2 h2 = bf2_to_f2(ah2), h3 = bf2_to_f2(ah3);
        uint32_t al0 = f2_to_bf2(make_float2(v0.x - h0.x, v0.y - h0.y));
        uint32_t al1 = f2_to_bf2(make_float2(v1.x - h1.x, v1.y - h1.y));
        uint32_t al2 = f2_to_bf2(make_float2(v2.x - h2.x, v2.y - h2.y));
        uint32_t al3 = f2_to_bf2(make_float2(v3.x - h3.x, v3.y - h3.y));

#pragma unroll
        for (int nt = 0; nt < 8; nt++) {
            uint2 bh = sB[buf][0][nt][lane];
            uint2 bl = sB[buf][1][nt][lane];
            MMA_BF16(acc[nt], ah0, ah1, ah2, ah3, bh.x, bh.y);
            MMA_BF16(acc[nt], al0, al1, al2, al3, bh.x, bh.y);
            MMA_BF16(acc[nt], ah0, ah1, ah2, ah3, bl.x, bl.y);
        }
    }

    const int ro0 = gm + warp * 16 + g;
    const int ro1 = ro0 + 8;
#pragma unroll
    for (int nt = 0; nt < 8; nt++) {
        int col = nt * 8 + tig * 2;
        float2 bv = __ldg((const float2*)&bp[col]);
        if (ro0 < n)
            *(float2*)&h[(size_t)ro0 * 64 + col] =
                make_float2(acc[nt][0] + bv.x, acc[nt][1] + bv.y);
        if (ro1 < n)
            *(float2*)&h[(size_t)ro1 * 64 + col] =
                make_float2(acc[nt][2] + bv.x, acc[nt][3] + bv.y);
    }
}

// =====================================================================
// qkv (HMMA): [q | kT' | mT] = h @ Wc + bc, bf16 out (R10 version)
// =====================================================================
__global__ __launch_bounds__(512, 2) void qkv_mma_kernel(
    const float* __restrict__ h,
    const uint2* __restrict__ gChi, const uint2* __restrict__ gClo,
    const float* __restrict__ bc,
    __nv_bfloat16* __restrict__ qo, __nv_bfloat16* __restrict__ kmo,
    int n, int l)
{
    __shared__ uint2 sBh[4][24][32];
    __shared__ uint2 sBl[4][24][32];

    const int tid = threadIdx.x;
    {
        const uint4* srch = (const uint4*)(gChi + l * 3072);
        const uint4* srcl = (const uint4*)(gClo + l * 3072);
        uint4* dh = (uint4*)sBh;
        uint4* dl = (uint4*)sBl;
#pragma unroll
        for (int i = 0; i < 3; i++) {
            dh[tid + i * 512] = srch[tid + i * 512];
            dl[tid + i * 512] = srcl[tid + i * 512];
        }
    }
    __syncthreads();

    const int warp = tid >> 5, lane = tid & 31;
    const int g = lane >> 2, tig = lane & 3;
    const int rowg = warp >> 1, colh = warp & 1;
    const int gm = blockIdx.x * 128;
    const int r0 = gm + rowg * 16 + g;
    const int r1 = r0 + 8;
    const int r0c = (r0 < n) ? r0 : n - 1;
    const int r1c = (r1 < n) ? r1 : n - 1;
    const float* bcl = bc + l * 192;

#pragma unroll
    for (int half = 0; half < 2; half++) {
        float acc[6][4];
#pragma unroll
        for (int i = 0; i < 6; i++)
#pragma unroll
            for (int j = 0; j < 4; j++) acc[i][j] = 0.f;

#pragma unroll
        for (int ch = 0; ch < 4; ch++) {
            int co = ch * 16 + tig * 2;
            float2 v0 = *(const float2*)&h[(size_t)r0c * 64 + co];
            float2 v1 = *(const float2*)&h[(size_t)r1c * 64 + co];
            float2 v2 = *(const float2*)&h[(size_t)r0c * 64 + co + 8];
            float2 v3 = *(const float2*)&h[(size_t)r1c * 64 + co + 8];

            uint32_t ah0 = f2_to_bf2(v0), ah1 = f2_to_bf2(v1);
            uint32_t ah2 = f2_to_bf2(v2), ah3 = f2_to_bf2(v3);
            float2 h0 = bf2_to_f2(ah0), h1 = bf2_to_f2(ah1);
            float2 h2 = bf2_to_f2(ah2), h3 = bf2_to_f2(ah3);
            uint32_t al0 = f2_to_bf2(make_float2(v0.x - h0.x, v0.y - h0.y));
            uint32_t al1 = f2_to_bf2(make_float2(v1.x - h1.x, v1.y - h1.y));
            uint32_t al2 = f2_to_bf2(make_float2(v2.x - h2.x, v2.y - h2.y));
            uint32_t al3 = f2_to_bf2(make_float2(v3.x - h3.x, v3.y - h3.y));

#pragma unroll
            for (int nt = 0; nt < 6; nt++) {
                int ng = colh * 12 + half * 6 + nt;
                uint2 bh = sBh[ch][ng][lane];
                uint2 bl = sBl[ch][ng][lane];
                MMA_BF16(acc[nt], ah0, ah1, ah2, ah3, bh.x, bh.y);
                MMA_BF16(acc[nt], al0, al1, al2, al3, bh.x, bh.y);
                MMA_BF16(acc[nt], ah0, ah1, ah2, ah3, bl.x, bl.y);
            }
        }

#pragma unroll
        for (int nt = 0; nt < 6; nt++) {
            int col = colh * 96 + half * 48 + nt * 8 + tig * 2;
            float2 b = __ldg((const float2*)&bcl[col]);
            __nv_bfloat162 o0 = __float22bfloat162_rn(
                make_float2(acc[nt][0] + b.x, acc[nt][1] + b.y));
            __nv_bfloat162 o1 = __float22bfloat162_rn(
                make_float2(acc[nt][2] + b.x, acc[nt][3] + b.y));
            if (col < 64) {
                if (r0 < n) *(__nv_bfloat162*)&qo[(size_t)r0 * 64 + col] = o0;
                if (r1 < n) *(__nv_bfloat162*)&qo[(size_t)r1 * 64 + col] = o1;
            } else {
                if (r0 < n) *(__nv_bfloat162*)&kmo[(size_t)r0 * 128 + col - 64] = o0;
                if (r1 < n) *(__nv_bfloat162*)&kmo[(size_t)r1 * 128 + col - 64] = o1;
            }
        }
    }
}

// =====================================================================
// CSR construction (R14 streamlined)
// =====================================================================
__global__ void zero_kernel(int* a, int n) {
    int i = blockIdx.x * blockDim.x + threadIdx.x;
    if (i < n) a[i] = 0;
}

__global__ void hist_kernel(const int* __restrict__ ei, int* __restrict__ cnt, int ne) {
    int e = blockIdx.x * blockDim.x + threadIdx.x;
    if (e < ne) atomicAdd(&cnt[ei[ne + e]], 1);
}

__global__ __launch_bounds__(1024) void scan1_kernel(
    const int* __restrict__ in, int* __restrict__ out, int* __restrict__ part, int n)
{
    __shared__ int wsum[32];
    int t = threadIdx.x;
    int i = blockIdx.x * 1024 + t;
    int v = (i < n) ? in[i] : 0;
    int x = v;
#pragma unroll
    for (int d = 1; d < 32; d <<= 1) {
        int y = __shfl_up_sync(0xffffffffu, x, d);
        if ((t & 31) >= d) x += y;
    }
    if ((t & 31) == 31) wsum[t >> 5] = x;
    __syncthreads();
    if (t < 32) {
        int s = wsum[t];
        int sx = s;
#pragma unroll
        for (int d = 1; d < 32; d <<= 1) {
            int y = __shfl_up_sync(0xffffffffu, sx, d);
            if (t >= d) sx += y;
        }
        wsum[t] = sx - s;
    }
    __syncthreads();
    int excl = x - v + wsum[t >> 5];
    if (i < n) out[i] = excl;
    if (t == 1023 && part) part[blockIdx.x] = x + wsum[31];
}

__global__ __launch_bounds__(1024) void scan3_kernel(
    int* __restrict__ off, int* __restrict__ offmut,
    const int* __restrict__ part, int n)
{
    __shared__ int sbase;
    int t = threadIdx.x;
    int bid = blockIdx.x;
    if (t < 32) {
        int s = 0;
        for (int j = t; j < bid; j += 32) s += part[j];
#pragma unroll
        for (int d = 16; d >= 1; d >>= 1)
            s += __shfl_xor_sync(0xffffffffu, s, d);
        if (t == 0) sbase = s;
    }
    __syncthreads();
    int i = bid * 1024 + t;
    if (i < n) {
        int v = off[i] + sbase;
        off[i] = v;
        offmut[i] = v;
    }
}

__global__ void scatter_kernel(const int* __restrict__ ei,
                               int* __restrict__ offmut,
                               int* __restrict__ csr, int ne)
{
    int e = blockIdx.x * blockDim.x + threadIdx.x;
    if (e < ne) {
        int s = ei[e];
        int d = ei[ne + e];
        int pos = atomicAdd(&offmut[d], 1);
        csr[pos] = s;
    }
}

// =====================================================================
// layer v7: head-per-lane edge loop. Warp = 8 edges x 4 heads; each
// lane computes its head's FULL dot in-lane (packed f32x2) — no shfl
// in the inner loop. One 3-step xor all-reduce over edge-slots per
// node at the end. HMMA g@Wo epilogue + optional fused classifier.
// =====================================================================
__global__ __launch_bounds__(256) void layer_kernel(
    const float* __restrict__ hin, const __nv_bfloat16* __restrict__ qb16,
    const __nv_bfloat16* __restrict__ km,
    const int* __restrict__ off, const int* __restrict__ cnt,
    const int* __restrict__ csr,
    const uint2* __restrict__ WoFhi, const uint2* __restrict__ WoFlo,
    const float* __restrict__ bo, const float* __restrict__ skp,
    float* __restrict__ hout,
    const float* __restrict__ Wc1, const float* __restrict__ bc1,
    const float* __restrict__ Wc2, const float* __restrict__ bc2,
    float* __restrict__ clsOut, int n)
{
    __shared__ uint2    sWh[4][8][32];
    __shared__ uint2    sWl[4][8][32];
    __shared__ uint32_t gsmh[8][33];
    __shared__ uint32_t gsml[8][33];
    __shared__ float    hsm[8][66];
    __shared__ float    sWc1[64 * 32];

    const int tid = threadIdx.x;
#pragma unroll
    for (int i = 0; i < 4; i++) {
        ((uint2*)sWh)[tid + i * 256] = WoFhi[tid + i * 256];
        ((uint2*)sWl)[tid + i * 256] = WoFlo[tid + i * 256];
    }
    const bool doCls = (clsOut != nullptr);
    if (doCls) {
        float4* dst = (float4*)sWc1;
        const float4* src = (const float4*)Wc1;
        dst[tid]       = src[tid];
        dst[tid + 256] = src[tid + 256];
    }

    const int w    = tid >> 5;
    const int lane = tid & 31;
    const int node = blockIdx.x * 8 + w;
    const bool valid = node < n;
    const int nodec = valid ? node : 0;

    const int es = lane >> 2;       // edge slot 0..7
    const int hd = lane & 3;        // head 0..3
    const int c0 = hd * 16;         // 16 bf16 cols for this head

    // q for this head: 16 cols -> 8 packed f32x2
    ull q[8];
    {
        uint4 q0 = *(const uint4*)&qb16[(size_t)nodec * 64 + c0];
        uint4 q1 = *(const uint4*)&qb16[(size_t)nodec * 64 + c0 + 8];
        q[0] = bf2_to_f2x2(q0.x); q[1] = bf2_to_f2x2(q0.y);
        q[2] = bf2_to_f2x2(q0.z); q[3] = bf2_to_f2x2(q0.w);
        q[4] = bf2_to_f2x2(q1.x); q[5] = bf2_to_f2x2(q1.y);
        q[6] = bf2_to_f2x2(q1.z); q[7] = bf2_to_f2x2(q1.w);
    }

    const int base = off[nodec];
    const int deg  = valid ? cnt[nodec] : 0;

    ull acc[8];
#pragma unroll
    for (int i = 0; i < 8; i++) acc[i] = 0ull;
    float wsum = 0.f;

    for (int i0 = 0; i0 < deg; i0 += 32) {
        int idx  = i0 + lane;
        int sreg = (idx < deg) ? csr[base + idx] : 0;
        int m = deg - i0; if (m > 32) m = 32;
#pragma unroll 2
        for (int jj = 0; jj < m; jj += 8) {
            int e  = jj + es;
            bool ok = (e < m);
            int s = __shfl_sync(0xffffffffu, sreg, e);
            if (!ok) s = 0;
            const __nv_bfloat16* row = km + (size_t)s * 128;
            uint4 ku0 = *(const uint4*)(row + c0);
            uint4 ku1 = *(const uint4*)(row + c0 + 8);
            uint4 mu0 = *(const uint4*)(row + 64 + c0);
            uint4 mu1 = *(const uint4*)(row + 64 + c0 + 8);

            // full head dot product, in-lane (packed f32x2)
            ull p0 = fma2(bf2_to_f2x2(ku0.x), q[0], 0ull);
            ull p1 = fma2(bf2_to_f2x2(ku0.y), q[1], 0ull);
            p0 = fma2(bf2_to_f2x2(ku0.z), q[2], p0);
            p1 = fma2(bf2_to_f2x2(ku0.w), q[3], p1);
            p0 = fma2(bf2_to_f2x2(ku1.x), q[4], p0);
            p1 = fma2(bf2_to_f2x2(ku1.y), q[5], p1);
            p0 = fma2(bf2_to_f2x2(ku1.z), q[6], p0);
            p1 = fma2(bf2_to_f2x2(ku1.w), q[7], p1);
            float2 pa = unpack2(p0), pb = unpack2(p1);
            float p = (pa.x + pa.y) + (pb.x + pb.y);

            float wgt = ok ? __expf(p) : 0.f;
            ull w2 = pack2(wgt, wgt);
            acc[0] = fma2(w2, bf2_to_f2x2(mu0.x), acc[0]);
            acc[1] = fma2(w2, bf2_to_f2x2(mu0.y), acc[1]);
            acc[2] = fma2(w2, bf2_to_f2x2(mu0.z), acc[2]);
            acc[3] = fma2(w2, bf2_to_f2x2(mu0.w), acc[3]);
            acc[4] = fma2(w2, bf2_to_f2x2(mu1.x), acc[4]);
            acc[5] = fma2(w2, bf2_to_f2x2(mu1.y), acc[5]);
            acc[6] = fma2(w2, bf2_to_f2x2(mu1.z), acc[6]);
            acc[7] = fma2(w2, bf2_to_f2x2(mu1.w), acc[7]);
            wsum += wgt;
        }
    }

    // all-reduce over the 8 edge slots (lanes hd, hd+4, ..., hd+28)
    const ull ONE2 = pack2(1.f, 1.f);
#pragma unroll
    for (int d = 4; d <= 16; d <<= 1) {
#pragma unroll
        for (int i = 0; i < 8; i++) {
            ull r = __shfl_xor_sync(0xffffffffu, acc[i], d);
            acc[i] = fma2(ONE2, r, acc[i]);
        }
        wsum += __shfl_xor_sync(0xffffffffu, wsum, d);
    }

    // lane (es, hd) handles cols hd*16 + 2*es, +1  (= acc[es])
    {
        const float inv = 1.0f / (wsum + 1e-16f);
        float2 pr = unpack2(acc[es]);
        float gx = gelu_tanh(pr.x * inv);
        float gy = gelu_tanh(pr.y * inv);
        uint32_t h0 = f2_to_bf2(make_float2(gx, gy));
        float2 r0 = bf2_to_f2(h0);
        uint32_t l0 = f2_to_bf2(make_float2(gx - r0.x, gy - r0.y));
        gsmh[w][hd * 8 + es] = h0;
        gsml[w][hd * 8 + es] = l0;
    }
    __syncthreads();

    // MMA epilogue: warp w computes n-tile w for all 8 nodes.
    const int gq = lane >> 2, tig = lane & 3;
    {
        float cfr[4] = {0.f, 0.f, 0.f, 0.f};
#pragma unroll
        for (int ch = 0; ch < 4; ch++) {
            uint32_t ah0 = gsmh[gq][ch * 8 + tig];
            uint32_t ah2 = gsmh[gq][ch * 8 + tig + 4];
            uint32_t al0 = gsml[gq][ch * 8 + tig];
            uint32_t al2 = gsml[gq][ch * 8 + tig + 4];
            uint2 bh = sWh[ch][w][lane];
            uint2 bl = sWl[ch][w][lane];
            MMA_BF16(cfr, ah0, 0u, ah2, 0u, bh.x, bh.y);
            MMA_BF16(cfr, al0, 0u, al2, 0u, bh.x, bh.y);
            MMA_BF16(cfr, ah0, 0u, ah2, 0u, bl.x, bl.y);
        }

        const int nd = blockIdx.x * 8 + gq;
        const int col = w * 8 + tig * 2;
        float2 b = __ldg((const float2*)&bo[col]);
        const float sg = 1.0f / (1.0f + __expf(-skp[0]));
        float o0 = cfr[0] + b.x;
        float o1 = cfr[1] + b.y;
        if (nd < n) {
            float2 hp = *(const float2*)&hin[(size_t)nd * 64 + col];
            float r0 = fmaxf(sg * o0 + (1.0f - sg) * hp.x, 0.f);
            float r1 = fmaxf(sg * o1 + (1.0f - sg) * hp.y, 0.f);
            if (!doCls) {
                *(float2*)&hout[(size_t)nd * 64 + col] = make_float2(r0, r1);
            } else {
                hsm[gq][col]     = r0;
                hsm[gq][col + 1] = r1;
            }
        }
    }

    if (doCls) {
        __syncthreads();
        const int nd2 = blockIdx.x * 8 + w;
        if (nd2 < n) {
            float hc = __ldg(&bc1[lane]);
#pragma unroll 8
            for (int j = 0; j < 64; j++) {
                hc = fmaf(hsm[w][j], sWc1[j * 32 + lane], hc);
            }
            hc = fmaxf(hc, 0.f);
            float2 w2 = __ldg((const float2*)&Wc2[lane * 2]);
            float o0 = hc * w2.x;
            float o1 = hc * w2.y;
#pragma unroll
            for (int m = 16; m >= 1; m >>= 1) {
                o0 += __shfl_xor_sync(0xffffffffu, o0, m);
                o1 += __shfl_xor_sync(0xffffffffu, o1, m);
            }
            if (lane == 0) {
                *(float2*)&clsOut[(size_t)nd2 * 2] =
                    make_float2(o0 + __ldg(&bc2[0]), o1 + __ldg(&bc2[1]));
            }
        }
    }
}

// =====================================================================
extern "C" void kernel_launch(void* const* d_in, const int* in_sizes, int n_in,
                              void* d_out, int out_size)
{
    const float* x     = (const float*)d_in[0];
    const int*   ei    = (const int*)  d_in[1];
    const float* Wp    = (const float*)d_in[2];
    const float* bp    = (const float*)d_in[3];
    const float* Wk    = (const float*)d_in[4];
    const float* bk    = (const float*)d_in[5];
    const float* Wq    = (const float*)d_in[6];
    const float* bq    = (const float*)d_in[7];
    const float* Wv    = (const float*)d_in[8];
    const float* bv    = (const float*)d_in[9];
    const float* a_rel = (const float*)d_in[10];
    const float* m_rel = (const float*)d_in[11];
    const float* p_rel = (const float*)d_in[12];
    const float* Wo    = (const float*)d_in[13];
    const float* bo    = (const float*)d_in[14];
    const float* skp   = (const float*)d_in[15];
    const float* Wc1   = (const float*)d_in[16];
    const float* bc1   = (const float*)d_in[17];
    const float* Wc2   = (const float*)d_in[18];
    const float* bc2   = (const float*)d_in[19];

    const int n  = in_sizes[0] / 768;
    const int ne = in_sizes[1] / 2;

    float *h0, *h1, *bcb;
    __nv_bfloat16 *kmb, *qbb;
    uint2 *bhi, *blo, *chi, *clo, *wofh, *wofl;
    int *cnt, *off, *offmut, *part, *csr;
    cudaGetSymbolAddress((void**)&h0,  g_h0);
    cudaGetSymbolAddress((void**)&h1,  g_h1);
    cudaGetSymbolAddress((void**)&qbb, g_qb);
    cudaGetSymbolAddress((void**)&kmb, g_km);
    cudaGetSymbolAddress((void**)&bhi, g_Bhi);
    cudaGetSymbolAddress((void**)&blo, g_Blo);
    cudaGetSymbolAddress((void**)&chi, g_Chi);
    cudaGetSymbolAddress((void**)&clo, g_Clo);
    cudaGetSymbolAddress((void**)&wofh, g_WoFhi);
    cudaGetSymbolAddress((void**)&wofl, g_WoFlo);
    cudaGetSymbolAddress((void**)&bcb, g_bc);
    cudaGetSymbolAddress((void**)&cnt, g_cnt);
    cudaGetSymbolAddress((void**)&off, g_off);
    cudaGetSymbolAddress((void**)&offmut, g_offmut);
    cudaGetSymbolAddress((void**)&part, g_part);
    cudaGetSymbolAddress((void**)&csr, g_csr);

    const int gProj = (n + 127) / 128;
    const int gQkv  = (n + 127) / 128;
    const int gWarp = (n + 7) / 8;
    const int gE    = (ne + 255) / 256;
    const int nScanBlocks = (n + 1023) / 1024;

    // Launch order: proj_mma at slot #4 (ncu profiles launch #4).
    wprep_kernel<<<48, 256>>>(Wp, bhi, blo);                                  // 1
    wcombpack_kernel<<<26, 256>>>(Wk, bk, Wq, bq, Wv, bv,                     // 2
                                  a_rel, m_rel, p_rel, chi, clo, bcb);
    woprep_kernel<<<8, 256>>>(Wo, wofh, wofl);                                // 3
    proj_mma_kernel<<<gProj, 256>>>(x, bp, bhi, blo, h0, n);                  // 4
    qkv_mma_kernel<<<gQkv, 512>>>(h0, chi, clo, bcb, qbb, kmb, n, 0);         // 5
    zero_kernel<<<(n + 255) / 256, 256>>>(cnt, n);                            // 6
    hist_kernel<<<gE, 256>>>(ei, cnt, ne);                                     // 7
    scan1_kernel<<<nScanBlocks, 1024>>>(cnt, off, part, n);                    // 8
    scan3_kernel<<<nScanBlocks, 1024>>>(off, offmut, part, n);                 // 9
    scatter_kernel<<<gE, 256>>>(ei, offmut, csr, ne);                          // 10

    layer_kernel<<<gWarp, 256>>>(h0, qbb, kmb, off, cnt, csr,                  // 11
                                 wofh, wofl, bo, skp, h1,
                                 nullptr, nullptr, nullptr, nullptr,
                                 nullptr, n);
    qkv_mma_kernel<<<gQkv, 512>>>(h1, chi, clo, bcb, qbb, kmb, n, 1);          // 12
    layer_kernel<<<gWarp, 256>>>(h1, qbb, kmb, off, cnt, csr,                  // 13
                                 wofh + 1024, wofl + 1024, bo + 64, skp + 1,
                                 h0, Wc1, bc1, Wc2, bc2, (float*)d_out, n);
}

// round 16
// speedup vs baseline: 1.0744x; 1.0744x over previous
#include <cuda_runtime.h>
#include <cuda_bf16.h>
#include <cstdint>

typedef unsigned long long ull;

#define NMAX 100032
#define EMAX 1664000
#define HID 64

// ---------------- packed fp32x2 helpers ----------------
__device__ __forceinline__ ull fma2(ull a, ull b, ull c) {
    ull d;
    asm("fma.rn.f32x2 %0, %1, %2, %3;" : "=l"(d) : "l"(a), "l"(b), "l"(c));
    return d;
}
__device__ __forceinline__ ull pack2(float x, float y) {
    ull r; asm("mov.b64 %0, {%1, %2};" : "=l"(r) : "f"(x), "f"(y)); return r;
}
__device__ __forceinline__ float2 unpack2(ull v) {
    float2 r; asm("mov.b64 {%0, %1}, %2;" : "=f"(r.x), "=f"(r.y) : "l"(v)); return r;
}

__device__ __forceinline__ void cp16(void* smem, const void* gmem) {
    unsigned saddr = (unsigned)__cvta_generic_to_shared(smem);
    asm volatile("cp.async.cg.shared.global [%0], [%1], 16;" :: "r"(saddr), "l"(gmem));
}
__device__ __forceinline__ void cp_commit() { asm volatile("cp.async.commit_group;"); }
template <int N>
__device__ __forceinline__ void cp_wait() { asm volatile("cp.async.wait_group %0;" :: "n"(N)); }

__device__ __forceinline__ float gelu_tanh(float x) {
    float x3 = x * x * x;
    return 0.5f * x * (1.0f + tanhf(0.79788456080286535588f * (x + 0.044715f * x3)));
}

// bf16 mma (sm_80+)
#define MMA_BF16(d, a0, a1, a2, a3, b0, b1) \
    asm volatile( \
        "mma.sync.aligned.m16n8k16.row.col.f32.bf16.bf16.f32 " \
        "{%0,%1,%2,%3},{%4,%5,%6,%7},{%8,%9},{%0,%1,%2,%3};" \
        : "+f"((d)[0]), "+f"((d)[1]), "+f"((d)[2]), "+f"((d)[3]) \
        : "r"(a0), "r"(a1), "r"(a2), "r"(a3), "r"(b0), "r"(b1))

__device__ __forceinline__ uint32_t f2_to_bf2(float2 v) {
    __nv_bfloat162 b = __float22bfloat162_rn(v);
    return *(uint32_t*)&b;
}
__device__ __forceinline__ float2 bf2_to_f2(uint32_t u) {
    return __bfloat1622float2(*(__nv_bfloat162*)&u);
}

// ---------------- scratch ----------------
__device__ float g_h0 [NMAX * HID];
__device__ float g_h1 [NMAX * HID];
__device__ __nv_bfloat16 g_qb [NMAX * 64];
__device__ __nv_bfloat16 g_km [NMAX * 128];   // layer-1 tables
__device__ __nv_bfloat16 g_qb2[NMAX * 64];
__device__ __nv_bfloat16 g_km2[NMAX * 128];   // layer-2 tables (written by layer1)
__device__ uint2 g_Bhi[48 * 8 * 32];
__device__ uint2 g_Blo[48 * 8 * 32];
__device__ uint2 g_Chi[2 * 4 * 24 * 32];
__device__ uint2 g_Clo[2 * 4 * 24 * 32];
__device__ uint2 g_WoFhi[2 * 4 * 8 * 32];
__device__ uint2 g_WoFlo[2 * 4 * 8 * 32];
__device__ float g_bc [2 * 192];
__device__ int   g_cnt [NMAX];
__device__ int   g_off [NMAX];
__device__ int   g_offmut[NMAX];
__device__ int   g_part[128];
__device__ int   g_csr [EMAX];

// =====================================================================
// W prep for proj
// =====================================================================
__global__ void wprep_kernel(const float* __restrict__ Wp,
                             uint2* __restrict__ bhi, uint2* __restrict__ blo)
{
    int e = blockIdx.x * 256 + threadIdx.x;
    if (e >= 48 * 8 * 32) return;
    int lane = e & 31;
    int nt   = (e >> 5) & 7;
    int t    = e >> 8;
    int g = lane >> 2, tig = lane & 3;
    int nn = nt * 8 + g;
    int kb = t * 16 + tig * 2;

    float v00 = Wp[(kb    ) * 64 + nn];
    float v01 = Wp[(kb + 1) * 64 + nn];
    float v10 = Wp[(kb + 8) * 64 + nn];
    float v11 = Wp[(kb + 9) * 64 + nn];

    uint32_t h0 = f2_to_bf2(make_float2(v00, v01));
    uint32_t h1 = f2_to_bf2(make_float2(v10, v11));
    float2 hf0 = bf2_to_f2(h0), hf1 = bf2_to_f2(h1);
    uint32_t l0 = f2_to_bf2(make_float2(v00 - hf0.x, v01 - hf0.y));
    uint32_t l1 = f2_to_bf2(make_float2(v10 - hf1.x, v11 - hf1.y));

    bhi[e] = make_uint2(h0, h1);
    blo[e] = make_uint2(l0, l1);
}

// =====================================================================
// Wo prep
// =====================================================================
__global__ void woprep_kernel(const float* __restrict__ Wo,
                              uint2* __restrict__ whi, uint2* __restrict__ wlo)
{
    int e = blockIdx.x * 256 + threadIdx.x;
    if (e >= 2048) return;
    int lane = e & 31;
    int nt   = (e >> 5) & 7;
    int ch   = (e >> 8) & 3;
    int l    = e >> 10;
    int g = lane >> 2, tig = lane & 3;
    int nn = nt * 8 + g;
    int kb = ch * 16 + tig * 2;
    const float* W = Wo + l * 4096;

    float v00 = W[(kb    ) * 64 + nn];
    float v01 = W[(kb + 1) * 64 + nn];
    float v10 = W[(kb + 8) * 64 + nn];
    float v11 = W[(kb + 9) * 64 + nn];

    uint32_t h0 = f2_to_bf2(make_float2(v00, v01));
    uint32_t h1 = f2_to_bf2(make_float2(v10, v11));
    float2 hf0 = bf2_to_f2(h0), hf1 = bf2_to_f2(h1);
    uint32_t l0 = f2_to_bf2(make_float2(v00 - hf0.x, v01 - hf0.y));
    uint32_t l1 = f2_to_bf2(make_float2(v10 - hf1.x, v11 - hf1.y));

    whi[e] = make_uint2(h0, h1);
    wlo[e] = make_uint2(l0, l1);
}

// =====================================================================
// Combined qkv weights (q | kT'*prel | mT), bias included
// =====================================================================
__device__ float wc_val(int l, int j, int c,
                        const float* Wk, const float* Wq, const float* Wv,
                        const float* Ar, const float* Mr, const float* prel)
{
    if (c < 64) return Wq[l * 4096 + j * 64 + c];
    if (c < 128) {
        int f = c - 64, hh = f >> 4, fi = f & 15;
        float s = 0.f;
#pragma unroll
        for (int d = 0; d < 16; d++)
            s += Wk[l * 4096 + j * 64 + hh * 16 + d] * Ar[l * 1024 + hh * 256 + d * 16 + fi];
        return s * (prel[l * 4 + hh] * 0.25f);
    }
    int f = c - 128, hh = f >> 4, fi = f & 15;
    float s = 0.f;
#pragma unroll
    for (int d = 0; d < 16; d++)
        s += Wv[l * 4096 + j * 64 + hh * 16 + d] * Mr[l * 1024 + hh * 256 + d * 16 + fi];
    return s;
}

__global__ void wcombpack_kernel(
    const float* __restrict__ Wk, const float* __restrict__ bk,
    const float* __restrict__ Wq, const float* __restrict__ bq,
    const float* __restrict__ Wv, const float* __restrict__ bv,
    const float* __restrict__ Ar, const float* __restrict__ Mr,
    const float* __restrict__ prel,
    uint2* __restrict__ chi, uint2* __restrict__ clo, float* __restrict__ bc)
{
    int e = blockIdx.x * 256 + threadIdx.x;
    if (e < 6144) {
        int lane = e & 31;
        int r    = e >> 5;
        int nt   = r % 24;
        int r2   = r / 24;
        int ch   = r2 & 3;
        int l    = r2 >> 2;
        int g = lane >> 2, tig = lane & 3;
        int nn = nt * 8 + g;
        int kb = ch * 16 + tig * 2;

        float v00 = wc_val(l, kb,     nn, Wk, Wq, Wv, Ar, Mr, prel);
        float v01 = wc_val(l, kb + 1, nn, Wk, Wq, Wv, Ar, Mr, prel);
        float v10 = wc_val(l, kb + 8, nn, Wk, Wq, Wv, Ar, Mr, prel);
        float v11 = wc_val(l, kb + 9, nn, Wk, Wq, Wv, Ar, Mr, prel);

        uint32_t h0 = f2_to_bf2(make_float2(v00, v01));
        uint32_t h1 = f2_to_bf2(make_float2(v10, v11));
        float2 hf0 = bf2_to_f2(h0), hf1 = bf2_to_f2(h1);
        uint32_t l0 = f2_to_bf2(make_float2(v00 - hf0.x, v01 - hf0.y));
        uint32_t l1 = f2_to_bf2(make_float2(v10 - hf1.x, v11 - hf1.y));
        chi[e] = make_uint2(h0, h1);
        clo[e] = make_uint2(l0, l1);
    } else if (e < 6144 + 384) {
        int e2 = e - 6144;
        int l = e2 / 192, c = e2 % 192;
        float v;
        if (c < 64) {
            v = bq[l * 64 + c];
        } else if (c < 128) {
            int f = c - 64, hh = f >> 4, fi = f & 15;
            float s = 0.f;
#pragma unroll
            for (int d = 0; d < 16; d++)
                s += bk[l * 64 + hh * 16 + d] * Ar[l * 1024 + hh * 256 + d * 16 + fi];
            v = s * (prel[l * 4 + hh] * 0.25f);
        } else {
            int f = c - 128, hh = f >> 4, fi = f & 15;
            float s = 0.f;
#pragma unroll
            for (int d = 0; d < 16; d++)
                s += bv[l * 64 + hh * 16 + d] * Mr[l * 1024 + hh * 256 + d * 16 + fi];
            v = s;
        }
        bc[e2] = v;
    }
}

// =====================================================================
// proj: h = x @ Wp + bp via bf16 3-term split HMMA (R11 version)
// =====================================================================
__device__ __forceinline__ int aswz(int row, int kp) {
    return row * 8 + (kp ^ ((row & 3) << 1));
}

__global__ __launch_bounds__(256) void proj_mma_kernel(
    const float* __restrict__ x, const float* __restrict__ bp,
    const uint2* __restrict__ gBhi, const uint2* __restrict__ gBlo,
    float* __restrict__ h, int n)
{
    __shared__ ull  sA[4][128 * 8];
    __shared__ uint2 sB[4][2][8][32];

    const int tid  = threadIdx.x;
    const int gm   = blockIdx.x * 128;
    const int warp = tid >> 5, lane = tid & 31;
    const int g    = lane >> 2, tig = lane & 3;
    const int rA0  = warp * 16 + g;
    const int rA1  = rA0 + 8;

    auto prefetch = [&](int t) {
        int buf = t & 3;
#pragma unroll
        for (int i = 0; i < 2; i++) {
            int c = tid + i * 256;
            int row = c >> 2;
            int kp2 = (c & 3) * 2;
            int slot = aswz(row, kp2);
            int grow = gm + row; if (grow >= n) grow = n - 1;
            cp16((char*)sA[buf] + slot * 8,
                 x + (size_t)grow * 768 + t * 16 + kp2 * 2);
        }
        {
            int hl = tid >> 7;
            int c  = tid & 127;
            const uint2* src = hl ? gBlo : gBhi;
            cp16((char*)&sB[buf][hl][0][0] + c * 16,
                 (const char*)(src + t * 256) + c * 16);
        }
    };

    float acc[8][4];
#pragma unroll
    for (int i = 0; i < 8; i++)
#pragma unroll
        for (int j = 0; j < 4; j++) acc[i][j] = 0.f;

    prefetch(0); cp_commit();
    prefetch(1); cp_commit();
    prefetch(2); cp_commit();

    for (int t = 0; t < 48; t++) {
        if (t + 2 < 48)      cp_wait<2>();
        else if (t + 1 < 48) cp_wait<1>();
        else                 cp_wait<0>();
        __syncthreads();
        if (t + 3 < 48) { prefetch(t + 3); cp_commit(); }

        const int buf = t & 3;
        float2 v0 = unpack2(sA[buf][aswz(rA0, tig    )]);
        float2 v1 = unpack2(sA[buf][aswz(rA1, tig    )]);
        float2 v2 = unpack2(sA[buf][aswz(rA0, tig + 4)]);
        float2 v3 = unpack2(sA[buf][aswz(rA1, tig + 4)]);

        uint32_t ah0 = f2_to_bf2(v0), ah1 = f2_to_bf2(v1);
        uint32_t ah2 = f2_to_bf2(v2), ah3 = f2_to_bf2(v3);
        float2 h0 = bf2_to_f2(ah0), h1 = bf2_to_f2(ah1);
        float2 h2 = bf2_to_f2(ah2), h3 = bf2_to_f2(ah3);
        uint32_t al0 = f2_to_bf2(make_float2(v0.x - h0.x, v0.y - h0.y));
        uint32_t al1 = f2_to_bf2(make_float2(v1.x - h1.x, v1.y - h1.y));
        uint32_t al2 = f2_to_bf2(make_float2(v2.x - h2.x, v2.y - h2.y));
        uint32_t al3 = f2_to_bf2(make_float2(v3.x - h3.x, v3.y - h3.y));

#pragma unroll
        for (int nt = 0; nt < 8; nt++) {
            uint2 bh = sB[buf][0][nt][lane];
            uint2 bl = sB[buf][1][nt][lane];
            MMA_BF16(acc[nt], ah0, ah1, ah2, ah3, bh.x, bh.y);
            MMA_BF16(acc[nt], al0, al1, al2, al3, bh.x, bh.y);
            MMA_BF16(acc[nt], ah0, ah1, ah2, ah3, bl.x, bl.y);
        }
    }

    const int ro0 = gm + warp * 16 + g;
    const int ro1 = ro0 + 8;
#pragma unroll
    for (int nt = 0; nt < 8; nt++) {
        int col = nt * 8 + tig * 2;
        float2 bv = __ldg((const float2*)&bp[col]);
        if (ro0 < n)
            *(float2*)&h[(size_t)ro0 * 64 + col] =
                make_float2(acc[nt][0] + bv.x, acc[nt][1] + bv.y);
        if (ro1 < n)
            *(float2*)&h[(size_t)ro1 * 64 + col] =
                make_float2(acc[nt][2] + bv.x, acc[nt][3] + bv.y);
    }
}

// =====================================================================
// qkv (HMMA): [q | kT' | mT] = h @ Wc + bc, bf16 out (layer 0 only now)
// =====================================================================
__global__ __launch_bounds__(512, 2) void qkv_mma_kernel(
    const float* __restrict__ h,
    const uint2* __restrict__ gChi, const uint2* __restrict__ gClo,
    const float* __restrict__ bc,
    __nv_bfloat16* __restrict__ qo, __nv_bfloat16* __restrict__ kmo,
    int n, int l)
{
    __shared__ uint2 sBh[4][24][32];
    __shared__ uint2 sBl[4][24][32];

    const int tid = threadIdx.x;
    {
        const uint4* srch = (const uint4*)(gChi + l * 3072);
        const uint4* srcl = (const uint4*)(gClo + l * 3072);
        uint4* dh = (uint4*)sBh;
        uint4* dl = (uint4*)sBl;
#pragma unroll
        for (int i = 0; i < 3; i++) {
            dh[tid + i * 512] = srch[tid + i * 512];
            dl[tid + i * 512] = srcl[tid + i * 512];
        }
    }
    __syncthreads();

    const int warp = tid >> 5, lane = tid & 31;
    const int g = lane >> 2, tig = lane & 3;
    const int rowg = warp >> 1, colh = warp & 1;
    const int gm = blockIdx.x * 128;
    const int r0 = gm + rowg * 16 + g;
    const int r1 = r0 + 8;
    const int r0c = (r0 < n) ? r0 : n - 1;
    const int r1c = (r1 < n) ? r1 : n - 1;
    const float* bcl = bc + l * 192;

#pragma unroll
    for (int half = 0; half < 2; half++) {
        float acc[6][4];
#pragma unroll
        for (int i = 0; i < 6; i++)
#pragma unroll
            for (int j = 0; j < 4; j++) acc[i][j] = 0.f;

#pragma unroll
        for (int ch = 0; ch < 4; ch++) {
            int co = ch * 16 + tig * 2;
            float2 v0 = *(const float2*)&h[(size_t)r0c * 64 + co];
            float2 v1 = *(const float2*)&h[(size_t)r1c * 64 + co];
            float2 v2 = *(const float2*)&h[(size_t)r0c * 64 + co + 8];
            float2 v3 = *(const float2*)&h[(size_t)r1c * 64 + co + 8];

            uint32_t ah0 = f2_to_bf2(v0), ah1 = f2_to_bf2(v1);
            uint32_t ah2 = f2_to_bf2(v2), ah3 = f2_to_bf2(v3);
            float2 h0 = bf2_to_f2(ah0), h1 = bf2_to_f2(ah1);
            float2 h2 = bf2_to_f2(ah2), h3 = bf2_to_f2(ah3);
            uint32_t al0 = f2_to_bf2(make_float2(v0.x - h0.x, v0.y - h0.y));
            uint32_t al1 = f2_to_bf2(make_float2(v1.x - h1.x, v1.y - h1.y));
            uint32_t al2 = f2_to_bf2(make_float2(v2.x - h2.x, v2.y - h2.y));
            uint32_t al3 = f2_to_bf2(make_float2(v3.x - h3.x, v3.y - h3.y));

#pragma unroll
            for (int nt = 0; nt < 6; nt++) {
                int ng = colh * 12 + half * 6 + nt;
                uint2 bh = sBh[ch][ng][lane];
                uint2 bl = sBl[ch][ng][lane];
                MMA_BF16(acc[nt], ah0, ah1, ah2, ah3, bh.x, bh.y);
                MMA_BF16(acc[nt], al0, al1, al2, al3, bh.x, bh.y);
                MMA_BF16(acc[nt], ah0, ah1, ah2, ah3, bl.x, bl.y);
            }
        }

#pragma unroll
        for (int nt = 0; nt < 6; nt++) {
            int col = colh * 96 + half * 48 + nt * 8 + tig * 2;
            float2 b = __ldg((const float2*)&bcl[col]);
            __nv_bfloat162 o0 = __float22bfloat162_rn(
                make_float2(acc[nt][0] + b.x, acc[nt][1] + b.y));
            __nv_bfloat162 o1 = __float22bfloat162_rn(
                make_float2(acc[nt][2] + b.x, acc[nt][3] + b.y));
            if (col < 64) {
                if (r0 < n) *(__nv_bfloat162*)&qo[(size_t)r0 * 64 + col] = o0;
                if (r1 < n) *(__nv_bfloat162*)&qo[(size_t)r1 * 64 + col] = o1;
            } else {
                if (r0 < n) *(__nv_bfloat162*)&kmo[(size_t)r0 * 128 + col - 64] = o0;
                if (r1 < n) *(__nv_bfloat162*)&kmo[(size_t)r1 * 128 + col - 64] = o1;
            }
        }
    }
}

// =====================================================================
// CSR construction (R14 streamlined)
// =====================================================================
__global__ void zero_kernel(int* a, int n) {
    int i = blockIdx.x * blockDim.x + threadIdx.x;
    if (i < n) a[i] = 0;
}

__global__ void hist_kernel(const int* __restrict__ ei, int* __restrict__ cnt, int ne) {
    int e = blockIdx.x * blockDim.x + threadIdx.x;
    if (e < ne) atomicAdd(&cnt[ei[ne + e]], 1);
}

__global__ __launch_bounds__(1024) void scan1_kernel(
    const int* __restrict__ in, int* __restrict__ out, int* __restrict__ part, int n)
{
    __shared__ int wsum[32];
    int t = threadIdx.x;
    int i = blockIdx.x * 1024 + t;
    int v = (i < n) ? in[i] : 0;
    int x = v;
#pragma unroll
    for (int d = 1; d < 32; d <<= 1) {
        int y = __shfl_up_sync(0xffffffffu, x, d);
        if ((t & 31) >= d) x += y;
    }
    if ((t & 31) == 31) wsum[t >> 5] = x;
    __syncthreads();
    if (t < 32) {
        int s = wsum[t];
        int sx = s;
#pragma unroll
        for (int d = 1; d < 32; d <<= 1) {
            int y = __shfl_up_sync(0xffffffffu, sx, d);
            if (t >= d) sx += y;
        }
        wsum[t] = sx - s;
    }
    __syncthreads();
    int excl = x - v + wsum[t >> 5];
    if (i < n) out[i] = excl;
    if (t == 1023 && part) part[blockIdx.x] = x + wsum[31];
}

__global__ __launch_bounds__(1024) void scan3_kernel(
    int* __restrict__ off, int* __restrict__ offmut,
    const int* __restrict__ part, int n)
{
    __shared__ int sbase;
    int t = threadIdx.x;
    int bid = blockIdx.x;
    if (t < 32) {
        int s = 0;
        for (int j = t; j < bid; j += 32) s += part[j];
#pragma unroll
        for (int d = 16; d >= 1; d >>= 1)
            s += __shfl_xor_sync(0xffffffffu, s, d);
        if (t == 0) sbase = s;
    }
    __syncthreads();
    int i = bid * 1024 + t;
    if (i < n) {
        int v = off[i] + sbase;
        off[i] = v;
        offmut[i] = v;
    }
}

__global__ void scatter_kernel(const int* __restrict__ ei,
                               int* __restrict__ offmut,
                               int* __restrict__ csr, int ne)
{
    int e = blockIdx.x * blockDim.x + threadIdx.x;
    if (e < ne) {
        int s = ei[e];
        int d = ei[ne + e];
        int pos = atomicAdd(&offmut[d], 1);
        csr[pos] = s;
    }
}

// =====================================================================
// layer (R14 edge loop + HMMA Wo epilogue) + fused tails:
//  - doQkv (layer 1): after Wo epilogue, compute next layer's
//    [q|kT'|mT] = h1 @ Wc(l=1) from hsm via HMMA, B-frags from L2.
//  - doCls (layer 2): classifier from hsm.
// =====================================================================
__global__ __launch_bounds__(256) void layer_kernel(
    const float* __restrict__ hin, const __nv_bfloat16* __restrict__ qb16,
    const __nv_bfloat16* __restrict__ km,
    const int* __restrict__ off, const int* __restrict__ cnt,
    const int* __restrict__ csr,
    const uint2* __restrict__ WoFhi, const uint2* __restrict__ WoFlo,
    const float* __restrict__ bo, const float* __restrict__ skp,
    float* __restrict__ hout,
    const uint2* __restrict__ qChi, const uint2* __restrict__ qClo,
    const float* __restrict__ qbc,
    __nv_bfloat16* __restrict__ qo2, __nv_bfloat16* __restrict__ kmo2,
    const float* __restrict__ Wc1, const float* __restrict__ bc1,
    const float* __restrict__ Wc2, const float* __restrict__ bc2,
    float* __restrict__ clsOut, int n)
{
    __shared__ uint2    sWh[4][8][32];
    __shared__ uint2    sWl[4][8][32];
    __shared__ uint32_t gsmh[8][33];
    __shared__ uint32_t gsml[8][33];
    __shared__ float    hsm[8][66];
    __shared__ float    sWc1[64 * 32];

    const int tid = threadIdx.x;
#pragma unroll
    for (int i = 0; i < 4; i++) {
        ((uint2*)sWh)[tid + i * 256] = WoFhi[tid + i * 256];
        ((uint2*)sWl)[tid + i * 256] = WoFlo[tid + i * 256];
    }
    const bool doCls = (clsOut != nullptr);
    const bool doQkv = (qo2 != nullptr);
    if (doCls) {
        float4* dst = (float4*)sWc1;
        const float4* src = (const float4*)Wc1;
        dst[tid]       = src[tid];
        dst[tid + 256] = src[tid + 256];
    }

    const int w    = tid >> 5;
    const int lane = tid & 31;
    const int node = blockIdx.x * 8 + w;
    const bool valid = node < n;
    const int nodec = valid ? node : 0;

    const int sub = lane >> 4;
    const int sl  = lane & 15;
    const int c0  = sl * 4;

    uint2 qu = *(const uint2*)&qb16[(size_t)nodec * 64 + c0];
    float2 q01 = bf2_to_f2(qu.x), q23 = bf2_to_f2(qu.y);
    const float4 qv = make_float4(q01.x, q01.y, q23.x, q23.y);

    const int base = off[nodec];
    const int deg  = valid ? cnt[nodec] : 0;

    float4 acc = make_float4(0.f, 0.f, 0.f, 0.f);
    float wsum = 0.f;

    for (int i0 = 0; i0 < deg; i0 += 32) {
        int idx  = i0 + lane;
        int sreg = (idx < deg) ? csr[base + idx] : 0;
        int m = deg - i0; if (m > 32) m = 32;
#pragma unroll 4
        for (int jj = 0; jj < m; jj += 2) {
            int e  = jj + sub;
            bool ok = (e < m);
            int s = __shfl_sync(0xffffffffu, sreg, e);
            if (!ok) s = 0;
            const __nv_bfloat16* row = km + (size_t)s * 128;
            uint2 ku = *(const uint2*)(row + c0);
            uint2 mu = *(const uint2*)(row + 64 + c0);
            float2 k01 = bf2_to_f2(ku.x);
            float2 k23 = bf2_to_f2(ku.y);
            float2 m01 = bf2_to_f2(mu.x);
            float2 m23 = bf2_to_f2(mu.y);
            float p = k01.x * qv.x + k01.y * qv.y + k23.x * qv.z + k23.y * qv.w;
            p += __shfl_xor_sync(0xffffffffu, p, 1);
            p += __shfl_xor_sync(0xffffffffu, p, 2);
            float wgt = ok ? __expf(p) : 0.f;
            acc.x = fmaf(wgt, m01.x, acc.x);
            acc.y = fmaf(wgt, m01.y, acc.y);
            acc.z = fmaf(wgt, m23.x, acc.z);
            acc.w = fmaf(wgt, m23.y, acc.w);
            wsum += wgt;
        }
    }

    acc.x += __shfl_xor_sync(0xffffffffu, acc.x, 16);
    acc.y += __shfl_xor_sync(0xffffffffu, acc.y, 16);
    acc.z += __shfl_xor_sync(0xffffffffu, acc.z, 16);
    acc.w += __shfl_xor_sync(0xffffffffu, acc.w, 16);
    wsum  += __shfl_xor_sync(0xffffffffu, wsum, 16);

    const float inv = 1.0f / (wsum + 1e-16f);
    float4 g;
    g.x = gelu_tanh(acc.x * inv);
    g.y = gelu_tanh(acc.y * inv);
    g.z = gelu_tanh(acc.z * inv);
    g.w = gelu_tanh(acc.w * inv);

    if (lane < 16) {
        uint32_t h0 = f2_to_bf2(make_float2(g.x, g.y));
        uint32_t h1 = f2_to_bf2(make_float2(g.z, g.w));
        float2 r0 = bf2_to_f2(h0), r1 = bf2_to_f2(h1);
        uint32_t l0 = f2_to_bf2(make_float2(g.x - r0.x, g.y - r0.y));
        uint32_t l1 = f2_to_bf2(make_float2(g.z - r1.x, g.w - r1.y));
        gsmh[w][sl * 2]     = h0;
        gsmh[w][sl * 2 + 1] = h1;
        gsml[w][sl * 2]     = l0;
        gsml[w][sl * 2 + 1] = l1;
    }
    __syncthreads();

    // MMA Wo epilogue: warp w computes n-tile w for all 8 nodes.
    const int gq = lane >> 2, tig = lane & 3;
    {
        float cfr[4] = {0.f, 0.f, 0.f, 0.f};
#pragma unroll
        for (int ch = 0; ch < 4; ch++) {
            uint32_t ah0 = gsmh[gq][ch * 8 + tig];
            uint32_t ah2 = gsmh[gq][ch * 8 + tig + 4];
            uint32_t al0 = gsml[gq][ch * 8 + tig];
            uint32_t al2 = gsml[gq][ch * 8 + tig + 4];
            uint2 bh = sWh[ch][w][lane];
            uint2 bl = sWl[ch][w][lane];
            MMA_BF16(cfr, ah0, 0u, ah2, 0u, bh.x, bh.y);
            MMA_BF16(cfr, al0, 0u, al2, 0u, bh.x, bh.y);
            MMA_BF16(cfr, ah0, 0u, ah2, 0u, bl.x, bl.y);
        }

        const int nd = blockIdx.x * 8 + gq;
        const int col = w * 8 + tig * 2;
        float2 b = __ldg((const float2*)&bo[col]);
        const float sg = 1.0f / (1.0f + __expf(-skp[0]));
        float o0 = cfr[0] + b.x;
        float o1 = cfr[1] + b.y;
        if (nd < n) {
            float2 hp = *(const float2*)&hin[(size_t)nd * 64 + col];
            float r0 = fmaxf(sg * o0 + (1.0f - sg) * hp.x, 0.f);
            float r1 = fmaxf(sg * o1 + (1.0f - sg) * hp.y, 0.f);
            if (hout)
                *(float2*)&hout[(size_t)nd * 64 + col] = make_float2(r0, r1);
            if (doCls || doQkv) {
                hsm[gq][col]     = r0;
                hsm[gq][col + 1] = r1;
            }
        }
    }

    // Fused next-layer qkv: [q|kT'|mT] = h1 @ Wc(l=1) from hsm.
    // Warp w computes ntiles w*3 .. w*3+2 for the block's 8 nodes.
    if (doQkv) {
        __syncthreads();
        const int nd3 = blockIdx.x * 8 + gq;
        float qa[3][4];
#pragma unroll
        for (int i = 0; i < 3; i++)
#pragma unroll
            for (int j = 0; j < 4; j++) qa[i][j] = 0.f;

#pragma unroll
        for (int ch = 0; ch < 4; ch++) {
            float2 v0 = *(const float2*)&hsm[gq][ch * 16 + tig * 2];
            float2 v2 = *(const float2*)&hsm[gq][ch * 16 + 8 + tig * 2];
            uint32_t ah0 = f2_to_bf2(v0);
            uint32_t ah2 = f2_to_bf2(v2);
            float2 rr0 = bf2_to_f2(ah0), rr2 = bf2_to_f2(ah2);
            uint32_t al0 = f2_to_bf2(make_float2(v0.x - rr0.x, v0.y - rr0.y));
            uint32_t al2 = f2_to_bf2(make_float2(v2.x - rr2.x, v2.y - rr2.y));
#pragma unroll
            for (int t3 = 0; t3 < 3; t3++) {
                int ng = w * 3 + t3;
                uint2 bh = __ldg(&qChi[ch * 768 + ng * 32 + lane]);
                uint2 bl = __ldg(&qClo[ch * 768 + ng * 32 + lane]);
                MMA_BF16(qa[t3], ah0, 0u, ah2, 0u, bh.x, bh.y);
                MMA_BF16(qa[t3], al0, 0u, al2, 0u, bh.x, bh.y);
                MMA_BF16(qa[t3], ah0, 0u, ah2, 0u, bl.x, bl.y);
            }
        }
        if (nd3 < n) {
#pragma unroll
            for (int t3 = 0; t3 < 3; t3++) {
                int ng = w * 3 + t3;
                int col = ng * 8 + tig * 2;
                float2 b = __ldg((const float2*)&qbc[col]);
                __nv_bfloat162 o = __float22bfloat162_rn(
                    make_float2(qa[t3][0] + b.x, qa[t3][1] + b.y));
                if (col < 64)
                    *(__nv_bfloat162*)&qo2[(size_t)nd3 * 64 + col] = o;
                else
                    *(__nv_bfloat162*)&kmo2[(size_t)nd3 * 128 + col - 64] = o;
            }
        }
    }

    if (doCls) {
        __syncthreads();
        const int nd2 = blockIdx.x * 8 + w;
        if (nd2 < n) {
            float hc = __ldg(&bc1[lane]);
#pragma unroll 8
            for (int j = 0; j < 64; j++) {
                hc = fmaf(hsm[w][j], sWc1[j * 32 + lane], hc);
            }
            hc = fmaxf(hc, 0.f);
            float2 w2 = __ldg((const float2*)&Wc2[lane * 2]);
            float o0 = hc * w2.x;
            float o1 = hc * w2.y;
#pragma unroll
            for (int m = 16; m >= 1; m >>= 1) {
                o0 += __shfl_xor_sync(0xffffffffu, o0, m);
                o1 += __shfl_xor_sync(0xffffffffu, o1, m);
            }
            if (lane == 0) {
                *(float2*)&clsOut[(size_t)nd2 * 2] =
                    make_float2(o0 + __ldg(&bc2[0]), o1 + __ldg(&bc2[1]));
            }
        }
    }
}

// =====================================================================
extern "C" void kernel_launch(void* const* d_in, const int* in_sizes, int n_in,
                              void* d_out, int out_size)
{
    const float* x     = (const float*)d_in[0];
    const int*   ei    = (const int*)  d_in[1];
    const float* Wp    = (const float*)d_in[2];
    const float* bp    = (const float*)d_in[3];
    const float* Wk    = (const float*)d_in[4];
    const float* bk    = (const float*)d_in[5];
    const float* Wq    = (const float*)d_in[6];
    const float* bq    = (const float*)d_in[7];
    const float* Wv    = (const float*)d_in[8];
    const float* bv    = (const float*)d_in[9];
    const float* a_rel = (const float*)d_in[10];
    const float* m_rel = (const float*)d_in[11];
    const float* p_rel = (const float*)d_in[12];
    const float* Wo    = (const float*)d_in[13];
    const float* bo    = (const float*)d_in[14];
    const float* skp   = (const float*)d_in[15];
    const float* Wc1   = (const float*)d_in[16];
    const float* bc1   = (const float*)d_in[17];
    const float* Wc2   = (const float*)d_in[18];
    const float* bc2   = (const float*)d_in[19];

    const int n  = in_sizes[0] / 768;
    const int ne = in_sizes[1] / 2;

    float *h0, *h1, *bcb;
    __nv_bfloat16 *kmb, *qbb, *kmb2, *qbb2;
    uint2 *bhi, *blo, *chi, *clo, *wofh, *wofl;
    int *cnt, *off, *offmut, *part, *csr;
    cudaGetSymbolAddress((void**)&h0,  g_h0);
    cudaGetSymbolAddress((void**)&h1,  g_h1);
    cudaGetSymbolAddress((void**)&qbb, g_qb);
    cudaGetSymbolAddress((void**)&kmb, g_km);
    cudaGetSymbolAddress((void**)&qbb2, g_qb2);
    cudaGetSymbolAddress((void**)&kmb2, g_km2);
    cudaGetSymbolAddress((void**)&bhi, g_Bhi);
    cudaGetSymbolAddress((void**)&blo, g_Blo);
    cudaGetSymbolAddress((void**)&chi, g_Chi);
    cudaGetSymbolAddress((void**)&clo, g_Clo);
    cudaGetSymbolAddress((void**)&wofh, g_WoFhi);
    cudaGetSymbolAddress((void**)&wofl, g_WoFlo);
    cudaGetSymbolAddress((void**)&bcb, g_bc);
    cudaGetSymbolAddress((void**)&cnt, g_cnt);
    cudaGetSymbolAddress((void**)&off, g_off);
    cudaGetSymbolAddress((void**)&offmut, g_offmut);
    cudaGetSymbolAddress((void**)&part, g_part);
    cudaGetSymbolAddress((void**)&csr, g_csr);

    const int gProj = (n + 127) / 128;
    const int gQkv  = (n + 127) / 128;
    const int gWarp = (n + 7) / 8;
    const int gE    = (ne + 255) / 256;
    const int nScanBlocks = (n + 1023) / 1024;

    // Launch order: proj_mma at slot #4 (ncu profiles launch #4).
    wprep_kernel<<<48, 256>>>(Wp, bhi, blo);                                  // 1
    wcombpack_kernel<<<26, 256>>>(Wk, bk, Wq, bq, Wv, bv,                     // 2
                                  a_rel, m_rel, p_rel, chi, clo, bcb);
    woprep_kernel<<<8, 256>>>(Wo, wofh, wofl);                                // 3
    proj_mma_kernel<<<gProj, 256>>>(x, bp, bhi, blo, h0, n);                  // 4
    qkv_mma_kernel<<<gQkv, 512>>>(h0, chi, clo, bcb, qbb, kmb, n, 0);         // 5
    zero_kernel<<<(n + 255) / 256, 256>>>(cnt, n);                            // 6
    hist_kernel<<<gE, 256>>>(ei, cnt, ne);                                     // 7
    scan1_kernel<<<nScanBlocks, 1024>>>(cnt, off, part, n);                    // 8
    scan3_kernel<<<nScanBlocks, 1024>>>(off, offmut, part, n);                 // 9
    scatter_kernel<<<gE, 256>>>(ei, offmut, csr, ne);                          // 10

    // layer 1: edge+Wo epilogue + fused next-layer qkv (writes qb2/km2)
    layer_kernel<<<gWarp, 256>>>(h0, qbb, kmb, off, cnt, csr,                  // 11
                                 wofh, wofl, bo, skp, h1,
                                 chi + 3072, clo + 3072, bcb + 192,
                                 qbb2, kmb2,
                                 nullptr, nullptr, nullptr, nullptr,
                                 nullptr, n);
    // layer 2: edge+Wo epilogue + fused classifier -> d_out
    layer_kernel<<<gWarp, 256>>>(h1, qbb2, kmb2, off, cnt, csr,                // 12
                                 wofh + 1024, wofl + 1024, bo + 64, skp + 1,
                                 nullptr,
                                 nullptr, nullptr, nullptr, nullptr, nullptr,
                                 Wc1, bc1, Wc2, bc2, (float*)d_out, n);
}

// round 17
// speedup vs baseline: 1.1348x; 1.0562x over previous
#include <cuda_runtime.h>
#include <cuda_bf16.h>
#include <cstdint>

typedef unsigned long long ull;

#define NMAX 100032
#define EMAX 1664000
#define HID 64

// ---------------- packed fp32x2 helpers ----------------
__device__ __forceinline__ ull fma2(ull a, ull b, ull c) {
    ull d;
    asm("fma.rn.f32x2 %0, %1, %2, %3;" : "=l"(d) : "l"(a), "l"(b), "l"(c));
    return d;
}
__device__ __forceinline__ ull pack2(float x, float y) {
    ull r; asm("mov.b64 %0, {%1, %2};" : "=l"(r) : "f"(x), "f"(y)); return r;
}
__device__ __forceinline__ float2 unpack2(ull v) {
    float2 r; asm("mov.b64 {%0, %1}, %2;" : "=f"(r.x), "=f"(r.y) : "l"(v)); return r;
}

__device__ __forceinline__ void cp16(void* smem, const void* gmem) {
    unsigned saddr = (unsigned)__cvta_generic_to_shared(smem);
    asm volatile("cp.async.cg.shared.global [%0], [%1], 16;" :: "r"(saddr), "l"(gmem));
}
__device__ __forceinline__ void cp_commit() { asm volatile("cp.async.commit_group;"); }
template <int N>
__device__ __forceinline__ void cp_wait() { asm volatile("cp.async.wait_group %0;" :: "n"(N)); }

__device__ __forceinline__ float gelu_tanh(float x) {
    float x3 = x * x * x;
    return 0.5f * x * (1.0f + tanhf(0.79788456080286535588f * (x + 0.044715f * x3)));
}

// bf16 mma (sm_80+)
#define MMA_BF16(d, a0, a1, a2, a3, b0, b1) \
    asm volatile( \
        "mma.sync.aligned.m16n8k16.row.col.f32.bf16.bf16.f32 " \
        "{%0,%1,%2,%3},{%4,%5,%6,%7},{%8,%9},{%0,%1,%2,%3};" \
        : "+f"((d)[0]), "+f"((d)[1]), "+f"((d)[2]), "+f"((d)[3]) \
        : "r"(a0), "r"(a1), "r"(a2), "r"(a3), "r"(b0), "r"(b1))

__device__ __forceinline__ uint32_t f2_to_bf2(float2 v) {
    __nv_bfloat162 b = __float22bfloat162_rn(v);
    return *(uint32_t*)&b;
}
__device__ __forceinline__ float2 bf2_to_f2(uint32_t u) {
    return __bfloat1622float2(*(__nv_bfloat162*)&u);
}

// ---------------- scratch ----------------
__device__ float g_h0 [NMAX * HID];
__device__ float g_h1 [NMAX * HID];
__device__ __nv_bfloat16 g_qb[NMAX * 64];
__device__ __nv_bfloat16 g_km[NMAX * 128];   // [kT'(64) | mT(64)] per node
__device__ uint2 g_Bhi[48 * 8 * 32];
__device__ uint2 g_Blo[48 * 8 * 32];
__device__ uint2 g_Chi[2 * 4 * 24 * 32];
__device__ uint2 g_Clo[2 * 4 * 24 * 32];
__device__ uint2 g_WoFhi[2 * 4 * 8 * 32];
__device__ uint2 g_WoFlo[2 * 4 * 8 * 32];
__device__ float g_bc [2 * 192];
__device__ int   g_cnt [NMAX];
__device__ int   g_off [NMAX];
__device__ int   g_offmut[NMAX];
__device__ int   g_part[128];
__device__ int   g_csr [EMAX];

// =====================================================================
// W prep for proj
// =====================================================================
__global__ void wprep_kernel(const float* __restrict__ Wp,
                             uint2* __restrict__ bhi, uint2* __restrict__ blo)
{
    int e = blockIdx.x * 256 + threadIdx.x;
    if (e >= 48 * 8 * 32) return;
    int lane = e & 31;
    int nt   = (e >> 5) & 7;
    int t    = e >> 8;
    int g = lane >> 2, tig = lane & 3;
    int nn = nt * 8 + g;
    int kb = t * 16 + tig * 2;

    float v00 = Wp[(kb    ) * 64 + nn];
    float v01 = Wp[(kb + 1) * 64 + nn];
    float v10 = Wp[(kb + 8) * 64 + nn];
    float v11 = Wp[(kb + 9) * 64 + nn];

    uint32_t h0 = f2_to_bf2(make_float2(v00, v01));
    uint32_t h1 = f2_to_bf2(make_float2(v10, v11));
    float2 hf0 = bf2_to_f2(h0), hf1 = bf2_to_f2(h1);
    uint32_t l0 = f2_to_bf2(make_float2(v00 - hf0.x, v01 - hf0.y));
    uint32_t l1 = f2_to_bf2(make_float2(v10 - hf1.x, v11 - hf1.y));

    bhi[e] = make_uint2(h0, h1);
    blo[e] = make_uint2(l0, l1);
}

// =====================================================================
// Wo prep: pack Wo (2 layers, 64x64) into bf16 hi/lo B-frag images
// =====================================================================
__global__ void woprep_kernel(const float* __restrict__ Wo,
                              uint2* __restrict__ whi, uint2* __restrict__ wlo)
{
    int e = blockIdx.x * 256 + threadIdx.x;
    if (e >= 2048) return;
    int lane = e & 31;
    int nt   = (e >> 5) & 7;
    int ch   = (e >> 8) & 3;
    int l    = e >> 10;
    int g = lane >> 2, tig = lane & 3;
    int nn = nt * 8 + g;
    int kb = ch * 16 + tig * 2;
    const float* W = Wo + l * 4096;

    float v00 = W[(kb    ) * 64 + nn];
    float v01 = W[(kb + 1) * 64 + nn];
    float v10 = W[(kb + 8) * 64 + nn];
    float v11 = W[(kb + 9) * 64 + nn];

    uint32_t h0 = f2_to_bf2(make_float2(v00, v01));
    uint32_t h1 = f2_to_bf2(make_float2(v10, v11));
    float2 hf0 = bf2_to_f2(h0), hf1 = bf2_to_f2(h1);
    uint32_t l0 = f2_to_bf2(make_float2(v00 - hf0.x, v01 - hf0.y));
    uint32_t l1 = f2_to_bf2(make_float2(v10 - hf1.x, v11 - hf1.y));

    whi[e] = make_uint2(h0, h1);
    wlo[e] = make_uint2(l0, l1);
}

// =====================================================================
// Combined qkv weights (q | kT'*prel | mT), bias included
// =====================================================================
__device__ float wc_val(int l, int j, int c,
                        const float* Wk, const float* Wq, const float* Wv,
                        const float* Ar, const float* Mr, const float* prel)
{
    if (c < 64) return Wq[l * 4096 + j * 64 + c];
    if (c < 128) {
        int f = c - 64, hh = f >> 4, fi = f & 15;
        float s = 0.f;
#pragma unroll
        for (int d = 0; d < 16; d++)
            s += Wk[l * 4096 + j * 64 + hh * 16 + d] * Ar[l * 1024 + hh * 256 + d * 16 + fi];
        return s * (prel[l * 4 + hh] * 0.25f);
    }
    int f = c - 128, hh = f >> 4, fi = f & 15;
    float s = 0.f;
#pragma unroll
    for (int d = 0; d < 16; d++)
        s += Wv[l * 4096 + j * 64 + hh * 16 + d] * Mr[l * 1024 + hh * 256 + d * 16 + fi];
    return s;
}

__global__ void wcombpack_kernel(
    const float* __restrict__ Wk, const float* __restrict__ bk,
    const float* __restrict__ Wq, const float* __restrict__ bq,
    const float* __restrict__ Wv, const float* __restrict__ bv,
    const float* __restrict__ Ar, const float* __restrict__ Mr,
    const float* __restrict__ prel,
    uint2* __restrict__ chi, uint2* __restrict__ clo, float* __restrict__ bc)
{
    int e = blockIdx.x * 256 + threadIdx.x;
    if (e < 6144) {
        int lane = e & 31;
        int r    = e >> 5;
        int nt   = r % 24;
        int r2   = r / 24;
        int ch   = r2 & 3;
        int l    = r2 >> 2;
        int g = lane >> 2, tig = lane & 3;
        int nn = nt * 8 + g;
        int kb = ch * 16 + tig * 2;

        float v00 = wc_val(l, kb,     nn, Wk, Wq, Wv, Ar, Mr, prel);
        float v01 = wc_val(l, kb + 1, nn, Wk, Wq, Wv, Ar, Mr, prel);
        float v10 = wc_val(l, kb + 8, nn, Wk, Wq, Wv, Ar, Mr, prel);
        float v11 = wc_val(l, kb + 9, nn, Wk, Wq, Wv, Ar, Mr, prel);

        uint32_t h0 = f2_to_bf2(make_float2(v00, v01));
        uint32_t h1 = f2_to_bf2(make_float2(v10, v11));
        float2 hf0 = bf2_to_f2(h0), hf1 = bf2_to_f2(h1);
        uint32_t l0 = f2_to_bf2(make_float2(v00 - hf0.x, v01 - hf0.y));
        uint32_t l1 = f2_to_bf2(make_float2(v10 - hf1.x, v11 - hf1.y));
        chi[e] = make_uint2(h0, h1);
        clo[e] = make_uint2(l0, l1);
    } else if (e < 6144 + 384) {
        int e2 = e - 6144;
        int l = e2 / 192, c = e2 % 192;
        float v;
        if (c < 64) {
            v = bq[l * 64 + c];
        } else if (c < 128) {
            int f = c - 64, hh = f >> 4, fi = f & 15;
            float s = 0.f;
#pragma unroll
            for (int d = 0; d < 16; d++)
                s += bk[l * 64 + hh * 16 + d] * Ar[l * 1024 + hh * 256 + d * 16 + fi];
            v = s * (prel[l * 4 + hh] * 0.25f);
        } else {
            int f = c - 128, hh = f >> 4, fi = f & 15;
            float s = 0.f;
#pragma unroll
            for (int d = 0; d < 16; d++)
                s += bv[l * 64 + hh * 16 + d] * Mr[l * 1024 + hh * 256 + d * 16 + fi];
            v = s;
        }
        bc[e2] = v;
    }
}

// =====================================================================
// proj: h = x @ Wp + bp via bf16 3-term split HMMA (R11/R14 version)
// =====================================================================
__device__ __forceinline__ int aswz(int row, int kp) {
    return row * 8 + (kp ^ ((row & 3) << 1));
}

__global__ __launch_bounds__(256) void proj_mma_kernel(
    const float* __restrict__ x, const float* __restrict__ bp,
    const uint2* __restrict__ gBhi, const uint2* __restrict__ gBlo,
    float* __restrict__ h, int n)
{
    __shared__ ull  sA[4][128 * 8];
    __shared__ uint2 sB[4][2][8][32];

    const int tid  = threadIdx.x;
    const int gm   = blockIdx.x * 128;
    const int warp = tid >> 5, lane = tid & 31;
    const int g    = lane >> 2, tig = lane & 3;
    const int rA0  = warp * 16 + g;
    const int rA1  = rA0 + 8;

    auto prefetch = [&](int t) {
        int buf = t & 3;
#pragma unroll
        for (int i = 0; i < 2; i++) {
            int c = tid + i * 256;
            int row = c >> 2;
            int kp2 = (c & 3) * 2;
            int slot = aswz(row, kp2);
            int grow = gm + row; if (grow >= n) grow = n - 1;
            cp16((char*)sA[buf] + slot * 8,
                 x + (size_t)grow * 768 + t * 16 + kp2 * 2);
        }
        {
            int hl = tid >> 7;
            int c  = tid & 127;
            const uint2* src = hl ? gBlo : gBhi;
            cp16((char*)&sB[buf][hl][0][0] + c * 16,
                 (const char*)(src + t * 256) + c * 16);
        }
    };

    float acc[8][4];
#pragma unroll
    for (int i = 0; i < 8; i++)
#pragma unroll
        for (int j = 0; j < 4; j++) acc[i][j] = 0.f;

    prefetch(0); cp_commit();
    prefetch(1); cp_commit();
    prefetch(2); cp_commit();

    for (int t = 0; t < 48; t++) {
        if (t + 2 < 48)      cp_wait<2>();
        else if (t + 1 < 48) cp_wait<1>();
        else                 cp_wait<0>();
        __syncthreads();
        if (t + 3 < 48) { prefetch(t + 3); cp_commit(); }

        const int buf = t & 3;
        float2 v0 = unpack2(sA[buf][aswz(rA0, tig    )]);
        float2 v1 = unpack2(sA[buf][aswz(rA1, tig    )]);
        float2 v2 = unpack2(sA[buf][aswz(rA0, tig + 4)]);
        float2 v3 = unpack2(sA[buf][aswz(rA1, tig + 4)]);

        uint32_t ah0 = f2_to_bf2(v0), ah1 = f2_to_bf2(v1);
        uint32_t ah2 = f2_to_bf2(v2), ah3 = f2_to_bf2(v3);
        float2 h0 = bf2_to_f2(ah0), h1 = bf2_to_f2(ah1);
        float2 h2 = bf2_to_f2(ah2), h3 = bf2_to_f2(ah3);
        uint32_t al0 = f2_to_bf2(make_float2(v0.x - h0.x, v0.y - h0.y));
        uint32_t al1 = f2_to_bf2(make_float2(v1.x - h1.x, v1.y - h1.y));
        uint32_t al2 = f2_to_bf2(make_float2(v2.x - h2.x, v2.y - h2.y));
        uint32_t al3 = f2_to_bf2(make_float2(v3.x - h3.x, v3.y - h3.y));

#pragma unroll
        for (int nt = 0; nt < 8; nt++) {
            uint2 bh = sB[buf][0][nt][lane];
            uint2 bl = sB[buf][1][nt][lane];
            MMA_BF16(acc[nt], ah0, ah1, ah2, ah3, bh.x, bh.y);
            MMA_BF16(acc[nt], al0, al1, al2, al3, bh.x, bh.y);
            MMA_BF16(acc[nt], ah0, ah1, ah2, ah3, bl.x, bl.y);
        }
    }

    const int ro0 = gm + warp * 16 + g;
    const int ro1 = ro0 + 8;
#pragma unroll
    for (int nt = 0; nt < 8; nt++) {
        int col = nt * 8 + tig * 2;
        float2 bv = __ldg((const float2*)&bp[col]);
        if (ro0 < n)
            *(float2*)&h[(size_t)ro0 * 64 + col] =
                make_float2(acc[nt][0] + bv.x, acc[nt][1] + bv.y);
        if (ro1 < n)
            *(float2*)&h[(size_t)ro1 * 64 + col] =
                make_float2(acc[nt][2] + bv.x, acc[nt][3] + bv.y);
    }
}

// =====================================================================
// qkv (HMMA): [q | kT' | mT] = h @ Wc + bc, bf16 out (R10 version)
// =====================================================================
__global__ __launch_bounds__(512, 2) void qkv_mma_kernel(
    const float* __restrict__ h,
    const uint2* __restrict__ gChi, const uint2* __restrict__ gClo,
    const float* __restrict__ bc,
    __nv_bfloat16* __restrict__ qo, __nv_bfloat16* __restrict__ kmo,
    int n, int l)
{
    __shared__ uint2 sBh[4][24][32];
    __shared__ uint2 sBl[4][24][32];

    const int tid = threadIdx.x;
    {
        const uint4* srch = (const uint4*)(gChi + l * 3072);
        const uint4* srcl = (const uint4*)(gClo + l * 3072);
        uint4* dh = (uint4*)sBh;
        uint4* dl = (uint4*)sBl;
#pragma unroll
        for (int i = 0; i < 3; i++) {
            dh[tid + i * 512] = srch[tid + i * 512];
            dl[tid + i * 512] = srcl[tid + i * 512];
        }
    }
    __syncthreads();

    const int warp = tid >> 5, lane = tid & 31;
    const int g = lane >> 2, tig = lane & 3;
    const int rowg = warp >> 1, colh = warp & 1;
    const int gm = blockIdx.x * 128;
    const int r0 = gm + rowg * 16 + g;
    const int r1 = r0 + 8;
    const int r0c = (r0 < n) ? r0 : n - 1;
    const int r1c = (r1 < n) ? r1 : n - 1;
    const float* bcl = bc + l * 192;

#pragma unroll
    for (int half = 0; half < 2; half++) {
        float acc[6][4];
#pragma unroll
        for (int i = 0; i < 6; i++)
#pragma unroll
            for (int j = 0; j < 4; j++) acc[i][j] = 0.f;

#pragma unroll
        for (int ch = 0; ch < 4; ch++) {
            int co = ch * 16 + tig * 2;
            float2 v0 = *(const float2*)&h[(size_t)r0c * 64 + co];
            float2 v1 = *(const float2*)&h[(size_t)r1c * 64 + co];
            float2 v2 = *(const float2*)&h[(size_t)r0c * 64 + co + 8];
            float2 v3 = *(const float2*)&h[(size_t)r1c * 64 + co + 8];

            uint32_t ah0 = f2_to_bf2(v0), ah1 = f2_to_bf2(v1);
            uint32_t ah2 = f2_to_bf2(v2), ah3 = f2_to_bf2(v3);
            float2 h0 = bf2_to_f2(ah0), h1 = bf2_to_f2(ah1);
            float2 h2 = bf2_to_f2(ah2), h3 = bf2_to_f2(ah3);
            uint32_t al0 = f2_to_bf2(make_float2(v0.x - h0.x, v0.y - h0.y));
            uint32_t al1 = f2_to_bf2(make_float2(v1.x - h1.x, v1.y - h1.y));
            uint32_t al2 = f2_to_bf2(make_float2(v2.x - h2.x, v2.y - h2.y));
            uint32_t al3 = f2_to_bf2(make_float2(v3.x - h3.x, v3.y - h3.y));

#pragma unroll
            for (int nt = 0; nt < 6; nt++) {
                int ng = colh * 12 + half * 6 + nt;
                uint2 bh = sBh[ch][ng][lane];
                uint2 bl = sBl[ch][ng][lane];
                MMA_BF16(acc[nt], ah0, ah1, ah2, ah3, bh.x, bh.y);
                MMA_BF16(acc[nt], al0, al1, al2, al3, bh.x, bh.y);
                MMA_BF16(acc[nt], ah0, ah1, ah2, ah3, bl.x, bl.y);
            }
        }

#pragma unroll
        for (int nt = 0; nt < 6; nt++) {
            int col = colh * 96 + half * 48 + nt * 8 + tig * 2;
            float2 b = __ldg((const float2*)&bcl[col]);
            __nv_bfloat162 o0 = __float22bfloat162_rn(
                make_float2(acc[nt][0] + b.x, acc[nt][1] + b.y));
            __nv_bfloat162 o1 = __float22bfloat162_rn(
                make_float2(acc[nt][2] + b.x, acc[nt][3] + b.y));
            if (col < 64) {
                if (r0 < n) *(__nv_bfloat162*)&qo[(size_t)r0 * 64 + col] = o0;
                if (r1 < n) *(__nv_bfloat162*)&qo[(size_t)r1 * 64 + col] = o1;
            } else {
                if (r0 < n) *(__nv_bfloat162*)&kmo[(size_t)r0 * 128 + col - 64] = o0;
                if (r1 < n) *(__nv_bfloat162*)&kmo[(size_t)r1 * 128 + col - 64] = o1;
            }
        }
    }
}

// =====================================================================
// CSR construction (R14 streamlined)
// =====================================================================
__global__ void zero_kernel(int* a, int n) {
    int i = blockIdx.x * blockDim.x + threadIdx.x;
    if (i < n) a[i] = 0;
}

__global__ void hist_kernel(const int* __restrict__ ei, int* __restrict__ cnt, int ne) {
    int e = blockIdx.x * blockDim.x + threadIdx.x;
    if (e < ne) atomicAdd(&cnt[ei[ne + e]], 1);
}

__global__ __launch_bounds__(1024) void scan1_kernel(
    const int* __restrict__ in, int* __restrict__ out, int* __restrict__ part, int n)
{
    __shared__ int wsum[32];
    int t = threadIdx.x;
    int i = blockIdx.x * 1024 + t;
    int v = (i < n) ? in[i] : 0;
    int x = v;
#pragma unroll
    for (int d = 1; d < 32; d <<= 1) {
        int y = __shfl_up_sync(0xffffffffu, x, d);
        if ((t & 31) >= d) x += y;
    }
    if ((t & 31) == 31) wsum[t >> 5] = x;
    __syncthreads();
    if (t < 32) {
        int s = wsum[t];
        int sx = s;
#pragma unroll
        for (int d = 1; d < 32; d <<= 1) {
            int y = __shfl_up_sync(0xffffffffu, sx, d);
            if (t >= d) sx += y;
        }
        wsum[t] = sx - s;
    }
    __syncthreads();
    int excl = x - v + wsum[t >> 5];
    if (i < n) out[i] = excl;
    if (t == 1023 && part) part[blockIdx.x] = x + wsum[31];
}

__global__ __launch_bounds__(1024) void scan3_kernel(
    int* __restrict__ off, int* __restrict__ offmut,
    const int* __restrict__ part, int n)
{
    __shared__ int sbase;
    int t = threadIdx.x;
    int bid = blockIdx.x;
    if (t < 32) {
        int s = 0;
        for (int j = t; j < bid; j += 32) s += part[j];
#pragma unroll
        for (int d = 16; d >= 1; d >>= 1)
            s += __shfl_xor_sync(0xffffffffu, s, d);
        if (t == 0) sbase = s;
    }
    __syncthreads();
    int i = bid * 1024 + t;
    if (i < n) {
        int v = off[i] + sbase;
        off[i] = v;
        offmut[i] = v;
    }
}

__global__ void scatter_kernel(const int* __restrict__ ei,
                               int* __restrict__ offmut,
                               int* __restrict__ csr, int ne)
{
    int e = blockIdx.x * blockDim.x + threadIdx.x;
    if (e < ne) {
        int s = ei[e];
        int d = ei[ne + e];
        int pos = atomicAdd(&offmut[d], 1);
        csr[pos] = s;
    }
}

// =====================================================================
// layer (R14): edge loop + HMMA Wo epilogue; DOCLS template removes the
// classifier path (code, registers, and 10KB smem) from layer 1.
// =====================================================================
template <bool DOCLS>
__global__ __launch_bounds__(256) void layer_kernel(
    const float* __restrict__ hin, const __nv_bfloat16* __restrict__ qb16,
    const __nv_bfloat16* __restrict__ km,
    const int* __restrict__ off, const int* __restrict__ cnt,
    const int* __restrict__ csr,
    const uint2* __restrict__ WoFhi, const uint2* __restrict__ WoFlo,
    const float* __restrict__ bo, const float* __restrict__ skp,
    float* __restrict__ hout,
    const float* __restrict__ Wc1, const float* __restrict__ bc1,
    const float* __restrict__ Wc2, const float* __restrict__ bc2,
    float* __restrict__ clsOut, int n)
{
    __shared__ uint2    sWh[4][8][32];
    __shared__ uint2    sWl[4][8][32];
    __shared__ uint32_t gsmh[8][33];
    __shared__ uint32_t gsml[8][33];
    __shared__ float    hsm [DOCLS ? 8 : 1][66];
    __shared__ float    sWc1[DOCLS ? 64 * 32 : 1];

    const int tid = threadIdx.x;
#pragma unroll
    for (int i = 0; i < 4; i++) {
        ((uint2*)sWh)[tid + i * 256] = WoFhi[tid + i * 256];
        ((uint2*)sWl)[tid + i * 256] = WoFlo[tid + i * 256];
    }
    if (DOCLS) {
        float4* dst = (float4*)sWc1;
        const float4* src = (const float4*)Wc1;
        dst[tid]       = src[tid];
        dst[tid + 256] = src[tid + 256];
    }

    const int w    = tid >> 5;
    const int lane = tid & 31;
    const int node = blockIdx.x * 8 + w;
    const bool valid = node < n;
    const int nodec = valid ? node : 0;

    const int sub = lane >> 4;
    const int sl  = lane & 15;
    const int c0  = sl * 4;

    uint2 qu = *(const uint2*)&qb16[(size_t)nodec * 64 + c0];
    float2 q01 = bf2_to_f2(qu.x), q23 = bf2_to_f2(qu.y);
    const float4 qv = make_float4(q01.x, q01.y, q23.x, q23.y);

    const int base = off[nodec];
    const int deg  = valid ? cnt[nodec] : 0;

    float4 acc = make_float4(0.f, 0.f, 0.f, 0.f);
    float wsum = 0.f;

    for (int i0 = 0; i0 < deg; i0 += 32) {
        int idx  = i0 + lane;
        int sreg = (idx < deg) ? csr[base + idx] : 0;
        int m = deg - i0; if (m > 32) m = 32;
#pragma unroll 4
        for (int jj = 0; jj < m; jj += 2) {
            int e  = jj + sub;
            bool ok = (e < m);
            int s = __shfl_sync(0xffffffffu, sreg, e);
            if (!ok) s = 0;
            const __nv_bfloat16* row = km + (size_t)s * 128;
            uint2 ku = *(const uint2*)(row + c0);
            uint2 mu = *(const uint2*)(row + 64 + c0);
            float2 k01 = bf2_to_f2(ku.x);
            float2 k23 = bf2_to_f2(ku.y);
            float2 m01 = bf2_to_f2(mu.x);
            float2 m23 = bf2_to_f2(mu.y);
            float p = k01.x * qv.x + k01.y * qv.y + k23.x * qv.z + k23.y * qv.w;
            p += __shfl_xor_sync(0xffffffffu, p, 1);
            p += __shfl_xor_sync(0xffffffffu, p, 2);
            float wgt = ok ? __expf(p) : 0.f;
            acc.x = fmaf(wgt, m01.x, acc.x);
            acc.y = fmaf(wgt, m01.y, acc.y);
            acc.z = fmaf(wgt, m23.x, acc.z);
            acc.w = fmaf(wgt, m23.y, acc.w);
            wsum += wgt;
        }
    }

    acc.x += __shfl_xor_sync(0xffffffffu, acc.x, 16);
    acc.y += __shfl_xor_sync(0xffffffffu, acc.y, 16);
    acc.z += __shfl_xor_sync(0xffffffffu, acc.z, 16);
    acc.w += __shfl_xor_sync(0xffffffffu, acc.w, 16);
    wsum  += __shfl_xor_sync(0xffffffffu, wsum, 16);

    const float inv = 1.0f / (wsum + 1e-16f);
    float4 g;
    g.x = gelu_tanh(acc.x * inv);
    g.y = gelu_tanh(acc.y * inv);
    g.z = gelu_tanh(acc.z * inv);
    g.w = gelu_tanh(acc.w * inv);

    if (lane < 16) {
        uint32_t h0 = f2_to_bf2(make_float2(g.x, g.y));
        uint32_t h1 = f2_to_bf2(make_float2(g.z, g.w));
        float2 r0 = bf2_to_f2(h0), r1 = bf2_to_f2(h1);
        uint32_t l0 = f2_to_bf2(make_float2(g.x - r0.x, g.y - r0.y));
        uint32_t l1 = f2_to_bf2(make_float2(g.z - r1.x, g.w - r1.y));
        gsmh[w][sl * 2]     = h0;
        gsmh[w][sl * 2 + 1] = h1;
        gsml[w][sl * 2]     = l0;
        gsml[w][sl * 2 + 1] = l1;
    }
    __syncthreads();

    // MMA Wo epilogue: warp w computes n-tile w for all 8 nodes.
    const int gq = lane >> 2, tig = lane & 3;
    {
        float cfr[4] = {0.f, 0.f, 0.f, 0.f};
#pragma unroll
        for (int ch = 0; ch < 4; ch++) {
            uint32_t ah0 = gsmh[gq][ch * 8 + tig];
            uint32_t ah2 = gsmh[gq][ch * 8 + tig + 4];
            uint32_t al0 = gsml[gq][ch * 8 + tig];
            uint32_t al2 = gsml[gq][ch * 8 + tig + 4];
            uint2 bh = sWh[ch][w][lane];
            uint2 bl = sWl[ch][w][lane];
            MMA_BF16(cfr, ah0, 0u, ah2, 0u, bh.x, bh.y);
            MMA_BF16(cfr, al0, 0u, al2, 0u, bh.x, bh.y);
            MMA_BF16(cfr, ah0, 0u, ah2, 0u, bl.x, bl.y);
        }

        const int nd = blockIdx.x * 8 + gq;
        const int col = w * 8 + tig * 2;
        float2 b = __ldg((const float2*)&bo[col]);
        const float sg = 1.0f / (1.0f + __expf(-skp[0]));
        float o0 = cfr[0] + b.x;
        float o1 = cfr[1] + b.y;
        if (nd < n) {
            float2 hp = *(const float2*)&hin[(size_t)nd * 64 + col];
            float r0 = fmaxf(sg * o0 + (1.0f - sg) * hp.x, 0.f);
            float r1 = fmaxf(sg * o1 + (1.0f - sg) * hp.y, 0.f);
            if (!DOCLS) {
                *(float2*)&hout[(size_t)nd * 64 + col] = make_float2(r0, r1);
            } else {
                hsm[gq][col]     = r0;
                hsm[gq][col + 1] = r1;
            }
        }
    }

    if (DOCLS) {
        __syncthreads();
        const int nd2 = blockIdx.x * 8 + w;
        if (nd2 < n) {
            float hc = __ldg(&bc1[lane]);
#pragma unroll 8
            for (int j = 0; j < 64; j++) {
                hc = fmaf(hsm[w][j], sWc1[j * 32 + lane], hc);
            }
            hc = fmaxf(hc, 0.f);
            float2 w2 = __ldg((const float2*)&Wc2[lane * 2]);
            float o0 = hc * w2.x;
            float o1 = hc * w2.y;
#pragma unroll
            for (int m = 16; m >= 1; m >>= 1) {
                o0 += __shfl_xor_sync(0xffffffffu, o0, m);
                o1 += __shfl_xor_sync(0xffffffffu, o1, m);
            }
            if (lane == 0) {
                *(float2*)&clsOut[(size_t)nd2 * 2] =
                    make_float2(o0 + __ldg(&bc2[0]), o1 + __ldg(&bc2[1]));
            }
        }
    }
}

// =====================================================================
extern "C" void kernel_launch(void* const* d_in, const int* in_sizes, int n_in,
                              void* d_out, int out_size)
{
    const float* x     = (const float*)d_in[0];
    const int*   ei    = (const int*)  d_in[1];
    const float* Wp    = (const float*)d_in[2];
    const float* bp    = (const float*)d_in[3];
    const float* Wk    = (const float*)d_in[4];
    const float* bk    = (const float*)d_in[5];
    const float* Wq    = (const float*)d_in[6];
    const float* bq    = (const float*)d_in[7];
    const float* Wv    = (const float*)d_in[8];
    const float* bv    = (const float*)d_in[9];
    const float* a_rel = (const float*)d_in[10];
    const float* m_rel = (const float*)d_in[11];
    const float* p_rel = (const float*)d_in[12];
    const float* Wo    = (const float*)d_in[13];
    const float* bo    = (const float*)d_in[14];
    const float* skp   = (const float*)d_in[15];
    const float* Wc1   = (const float*)d_in[16];
    const float* bc1   = (const float*)d_in[17];
    const float* Wc2   = (const float*)d_in[18];
    const float* bc2   = (const float*)d_in[19];

    const int n  = in_sizes[0] / 768;
    const int ne = in_sizes[1] / 2;

    float *h0, *h1, *bcb;
    __nv_bfloat16 *kmb, *qbb;
    uint2 *bhi, *blo, *chi, *clo, *wofh, *wofl;
    int *cnt, *off, *offmut, *part, *csr;
    cudaGetSymbolAddress((void**)&h0,  g_h0);
    cudaGetSymbolAddress((void**)&h1,  g_h1);
    cudaGetSymbolAddress((void**)&qbb, g_qb);
    cudaGetSymbolAddress((void**)&kmb, g_km);
    cudaGetSymbolAddress((void**)&bhi, g_Bhi);
    cudaGetSymbolAddress((void**)&blo, g_Blo);
    cudaGetSymbolAddress((void**)&chi, g_Chi);
    cudaGetSymbolAddress((void**)&clo, g_Clo);
    cudaGetSymbolAddress((void**)&wofh, g_WoFhi);
    cudaGetSymbolAddress((void**)&wofl, g_WoFlo);
    cudaGetSymbolAddress((void**)&bcb, g_bc);
    cudaGetSymbolAddress((void**)&cnt, g_cnt);
    cudaGetSymbolAddress((void**)&off, g_off);
    cudaGetSymbolAddress((void**)&offmut, g_offmut);
    cudaGetSymbolAddress((void**)&part, g_part);
    cudaGetSymbolAddress((void**)&csr, g_csr);

    const int gProj = (n + 127) / 128;
    const int gQkv  = (n + 127) / 128;
    const int gWarp = (n + 7) / 8;
    const int gE    = (ne + 255) / 256;
    const int nScanBlocks = (n + 1023) / 1024;

    // Launch order: proj_mma at slot #4 (ncu profiles launch #4).
    wprep_kernel<<<48, 256>>>(Wp, bhi, blo);                                  // 1
    wcombpack_kernel<<<26, 256>>>(Wk, bk, Wq, bq, Wv, bv,                     // 2
                                  a_rel, m_rel, p_rel, chi, clo, bcb);
    woprep_kernel<<<8, 256>>>(Wo, wofh, wofl);                                // 3
    proj_mma_kernel<<<gProj, 256>>>(x, bp, bhi, blo, h0, n);                  // 4
    qkv_mma_kernel<<<gQkv, 512>>>(h0, chi, clo, bcb, qbb, kmb, n, 0);         // 5
    zero_kernel<<<(n + 255) / 256, 256>>>(cnt, n);                            // 6
    hist_kernel<<<gE, 256>>>(ei, cnt, ne);                                     // 7
    scan1_kernel<<<nScanBlocks, 1024>>>(cnt, off, part, n);                    // 8
    scan3_kernel<<<nScanBlocks, 1024>>>(off, offmut, part, n);                 // 9
    scatter_kernel<<<gE, 256>>>(ei, offmut, csr, ne);                          // 10

    layer_kernel<false><<<gWarp, 256>>>(h0, qbb, kmb, off, cnt, csr,           // 11
                                        wofh, wofl, bo, skp, h1,
                                        nullptr, nullptr, nullptr, nullptr,
                                        nullptr, n);
    qkv_mma_kernel<<<gQkv, 512>>>(h1, chi, clo, bcb, qbb, kmb, n, 1);          // 12
    layer_kernel<true><<<gWarp, 256>>>(h1, qbb, kmb, off, cnt, csr,            // 13
                                       wofh + 1024, wofl + 1024, bo + 64,
                                       skp + 1, nullptr,
                                       Wc1, bc1, Wc2, bc2, (float*)d_out, n);
}